// round 1
// baseline (speedup 1.0000x reference)
#include <cuda_runtime.h>
#include <math.h>

#define NSEQ 256
#define LL   512
#define NAA  21
#define DD   128
#define EDIM (NAA*DD)   // 2688

// ---------------- scratch (static device globals; no allocation) ----------------
__device__ __align__(16) float g_w[LL*LL];             // sigmoid'd 512x512 kernel matrix, 1 MB
__device__ __align__(16) float g_E[2*NSEQ][EDIM];      // E1 (seq<256) and E2, 5.5 MB
__device__ __align__(16) float g_S[2*NSEQ][NAA*NAA];   // per-seq 21x21 gram
__device__ __align__(16) float g_G1[(size_t)NSEQ*LL*NAA]; // G1[n1,l,c] = S1[n1, X1[n1,l], c]
__device__ __align__(16) float g_G2[(size_t)NSEQ*LL*NAA]; // G2[n2,l,c] = S2[n2, c, X2[n2,l]]
__device__ __align__(16) float g_d[2*NSEQ][LL];        // d1 / d2 diagonals
__device__ float g_rk[2*NSEQ];                          // rsqrt(k1), rsqrt(k2)

// ---------------- w = sigmoid(symmetric(w_param)) ----------------
__global__ void k_build_w(const float* __restrict__ wp) {
    int idx = blockIdx.x*blockDim.x + threadIdx.x;
    if (idx >= LL*LL) return;
    int i = idx >> 9, j = idx & (LL-1);
    float v = 0.f;
    if (i > j)      v = wp[i*(i-1)/2 + j];
    else if (j > i) v = wp[j*(j-1)/2 + i];
    g_w[idx] = 1.f / (1.f + expf(-v));
}

// ---------------- E[n] = b + sum_l W[l*21 + X[n,l], :] ----------------
// 512 blocks (256 for X1, 256 for X2), 672 threads, each owns one float4 column.
__global__ void k_E(const int* __restrict__ X1, const int* __restrict__ X2,
                    const float* __restrict__ W, const float* __restrict__ b) {
    int seq = blockIdx.x;
    const int* X = (seq < NSEQ) ? (X1 + seq*LL) : (X2 + (seq-NSEQ)*LL);
    int t = threadIdx.x;                 // 0..671
    __shared__ int sX[LL];
    for (int i = threadIdx.x; i < LL; i += blockDim.x) sX[i] = X[i];
    __syncthreads();
    float4 acc = ((const float4*)b)[t];
    #pragma unroll 4
    for (int l = 0; l < LL; l++) {
        const float4* row = (const float4*)(W + (size_t)(l*NAA + sX[l])*EDIM);
        float4 v = row[t];
        acc.x += v.x; acc.y += v.y; acc.z += v.z; acc.w += v.w;
    }
    ((float4*)g_E[seq])[t] = acc;
}

// ---------------- S[n,a,c] = E[n,a,:] . E[n,c,:] ----------------
__global__ void k_S() {
    int seq = blockIdx.x;
    __shared__ float sE[EDIM];
    for (int i = threadIdx.x; i < EDIM; i += blockDim.x) sE[i] = g_E[seq][i];
    __syncthreads();
    for (int e = threadIdx.x; e < NAA*NAA; e += blockDim.x) {
        int a = e / NAA, c = e - a*NAA;
        const float* pa = sE + a*DD;
        const float* pc = sE + c*DD;
        float s = 0.f;
        #pragma unroll 8
        for (int d = 0; d < DD; d++) s += pa[d]*pc[d];
        g_S[seq][e] = s;
    }
}

// ---------------- gather tables G1/G2 + diagonals d ----------------
__global__ void k_G(const int* __restrict__ X1, const int* __restrict__ X2) {
    int seq = blockIdx.x;
    __shared__ float sS[NAA*NAA];
    __shared__ int   sX[LL];
    const int* X = (seq < NSEQ) ? (X1 + seq*LL) : (X2 + (seq-NSEQ)*LL);
    for (int i = threadIdx.x; i < NAA*NAA; i += blockDim.x) sS[i] = g_S[seq][i];
    for (int i = threadIdx.x; i < LL; i += blockDim.x) sX[i] = X[i];
    __syncthreads();
    if (seq < NSEQ) {
        float* G = g_G1 + (size_t)seq*LL*NAA;
        for (int idx = threadIdx.x; idx < LL*NAA; idx += blockDim.x) {
            int l = idx / NAA, c = idx - l*NAA;
            G[idx] = sS[sX[l]*NAA + c];
        }
    } else {
        float* G = g_G2 + (size_t)(seq-NSEQ)*LL*NAA;
        for (int idx = threadIdx.x; idx < LL*NAA; idx += blockDim.x) {
            int l = idx / NAA, c = idx - l*NAA;
            G[idx] = sS[c*NAA + sX[l]];
        }
    }
    for (int l = threadIdx.x; l < LL; l += blockDim.x)
        g_d[seq][l] = sS[sX[l]*NAA + sX[l]];
}

// ---------------- rk[n] = rsqrt( d^T w d ) ----------------
__global__ void k_rk() {
    int seq = blockIdx.x;
    __shared__ float sd[LL];
    __shared__ float swsum[8];
    for (int i = threadIdx.x; i < LL; i += blockDim.x) sd[i] = g_d[seq][i];
    __syncthreads();
    int warp = threadIdx.x >> 5, lane = threadIdx.x & 31;
    float acc = 0.f;
    for (int i = warp; i < LL; i += 8) {
        const float* wr = g_w + (size_t)i*LL;
        float p = 0.f;
        #pragma unroll 4
        for (int j = lane; j < LL; j += 32) p += wr[j]*sd[j];
        #pragma unroll
        for (int o = 16; o; o >>= 1) p += __shfl_xor_sync(0xffffffffu, p, o);
        acc += sd[i]*p;   // identical on all lanes after butterfly
    }
    if (lane == 0) swsum[warp] = acc;
    __syncthreads();
    if (threadIdx.x == 0) {
        float t = 0.f;
        #pragma unroll
        for (int i = 0; i < 8; i++) t += swsum[i];
        g_rk[seq] = rsqrtf(t);
    }
}

// ---------------- main: K[n1,n2] = a^2 * subs^T w subs * rk1 * rk2 ----------------
// Block = (n1, 32-wide n2 tile). Phase 1 builds subs^T (512 x 32) in smem.
// Phase 2: register-blocked GEMM y = subs @ w (per 128-j tile), folded dot with subs.
// 256 threads; warp ty owns pairs ty*4..+3; lane tx owns j = jt*128 + tx*4..+3.
__global__ void __launch_bounds__(256, 2)
k_main(const int* __restrict__ X1, const int* __restrict__ X2,
       const float* __restrict__ a, float* __restrict__ out) {
    extern __shared__ float sm[];
    float* sSubsT = sm;                       // 512*32 floats
    float* sW     = sm + LL*32;               // 32*128 floats (union with sG1)
    float* sG1    = sm + LL*32;               // 512*21 floats (phase 1 only)
    int*   sX1    = (int*)(sm + LL*32 + LL*NAA); // 512 ints

    int tid = threadIdx.x;
    int n1 = blockIdx.y;
    int n2base = blockIdx.x * 32;

    // phase 1a: stage G1[n1] table + X1 row
    const float* G1p = g_G1 + (size_t)n1*LL*NAA;
    for (int i = tid; i < LL*NAA; i += 256) sG1[i] = G1p[i];
    for (int i = tid; i < LL; i += 256)     sX1[i] = X1[n1*LL + i];
    __syncthreads();

    // phase 1b: subs^T[l][p] = 0.5*(G1[l, X2[n2,l]] + G2[n2, l, X1[n1,l]])
    {
        int p  = tid & 31;
        int n2 = n2base + p;
        const int*   X2r = X2 + n2*LL;
        const float* G2p = g_G2 + (size_t)n2*LL*NAA;
        for (int l = (tid >> 5); l < LL; l += 8) {
            int x2 = X2r[l];
            float v = 0.5f*(sG1[l*NAA + x2] + G2p[l*NAA + sX1[l]]);
            sSubsT[l*32 + p] = v;
        }
    }
    // sG1 region is reused as sW; the sync at top of the first ic iteration guards it.

    int warp = tid >> 5, lane = tid & 31;
    float k0 = 0.f, k1v = 0.f, k2v = 0.f, k3 = 0.f;

    for (int jt = 0; jt < 4; jt++) {
        float y[4][4];
        #pragma unroll
        for (int u = 0; u < 4; u++)
            #pragma unroll
            for (int v = 0; v < 4; v++) y[u][v] = 0.f;

        for (int ic = 0; ic < 16; ic++) {
            __syncthreads();
            // stage w chunk: rows ic*32..+31, cols jt*128..+127 (4096 floats)
            #pragma unroll
            for (int q = 0; q < 4; q++) {
                int idx = tid + q*256;      // float4 index 0..1023
                int r   = idx >> 5;         // 32 float4 per 128-col row
                int c4  = idx & 31;
                ((float4*)sW)[idx] =
                    *(const float4*)(g_w + (size_t)(ic*32 + r)*LL + jt*128 + c4*4);
            }
            __syncthreads();
            #pragma unroll
            for (int ii = 0; ii < 32; ii++) {
                int i = ic*32 + ii;
                float4 sv = *(const float4*)(sSubsT + i*32 + warp*4);   // broadcast
                float4 wv = *(const float4*)(sW + ii*128 + lane*4);     // conflict-free
                y[0][0] += sv.x*wv.x; y[0][1] += sv.x*wv.y; y[0][2] += sv.x*wv.z; y[0][3] += sv.x*wv.w;
                y[1][0] += sv.y*wv.x; y[1][1] += sv.y*wv.y; y[1][2] += sv.y*wv.z; y[1][3] += sv.y*wv.w;
                y[2][0] += sv.z*wv.x; y[2][1] += sv.z*wv.y; y[2][2] += sv.z*wv.z; y[2][3] += sv.z*wv.w;
                y[3][0] += sv.w*wv.x; y[3][1] += sv.w*wv.y; y[3][2] += sv.w*wv.z; y[3][3] += sv.w*wv.w;
            }
        }
        // fold: k[p] += sum_j y[p][j] * subs[p][j]
        #pragma unroll
        for (int jj = 0; jj < 4; jj++) {
            int j = jt*128 + lane*4 + jj;
            float4 sj = *(const float4*)(sSubsT + j*32 + warp*4);
            k0  += y[0][jj]*sj.x;
            k1v += y[1][jj]*sj.y;
            k2v += y[2][jj]*sj.z;
            k3  += y[3][jj]*sj.w;
        }
    }

    // reduce the 4 pair-accumulators across the warp's 32 lanes
    #pragma unroll
    for (int o = 16; o; o >>= 1) {
        k0  += __shfl_down_sync(0xffffffffu, k0,  o);
        k1v += __shfl_down_sync(0xffffffffu, k1v, o);
        k2v += __shfl_down_sync(0xffffffffu, k2v, o);
        k3  += __shfl_down_sync(0xffffffffu, k3,  o);
    }
    if (lane == 0) {
        float a2  = a[0]*a[0];
        float rk1 = g_rk[n1];
        int p0 = n2base + warp*4;
        out[n1*256 + p0 + 0] = a2 * k0  * rk1 * g_rk[NSEQ + p0 + 0];
        out[n1*256 + p0 + 1] = a2 * k1v * rk1 * g_rk[NSEQ + p0 + 1];
        out[n1*256 + p0 + 2] = a2 * k2v * rk1 * g_rk[NSEQ + p0 + 2];
        out[n1*256 + p0 + 3] = a2 * k3  * rk1 * g_rk[NSEQ + p0 + 3];
    }
}

// ---------------- launch ----------------
extern "C" void kernel_launch(void* const* d_in, const int* in_sizes, int n_in,
                              void* d_out, int out_size) {
    const int*   X1 = (const int*)d_in[0];
    const int*   X2 = (const int*)d_in[1];
    const float* W  = (const float*)d_in[2];
    const float* b  = (const float*)d_in[3];
    const float* wp = (const float*)d_in[4];
    const float* a  = (const float*)d_in[5];
    float* out = (float*)d_out;

    const int SMEM_MAIN = (LL*32 + LL*NAA + LL) * 4;   // 110592 B
    cudaFuncSetAttribute(k_main, cudaFuncAttributeMaxDynamicSharedMemorySize, SMEM_MAIN);

    k_build_w<<<(LL*LL + 255)/256, 256>>>(wp);
    k_E<<<2*NSEQ, 672>>>(X1, X2, W, b);
    k_S<<<2*NSEQ, 256>>>();
    k_G<<<2*NSEQ, 256>>>(X1, X2);
    k_rk<<<2*NSEQ, 256>>>();
    k_main<<<dim3(8, 256), 256, SMEM_MAIN>>>(X1, X2, a, out);
}

// round 3
// speedup vs baseline: 1.3956x; 1.3956x over previous
#include <cuda_runtime.h>
#include <math.h>
#include <cstdint>

#define NSEQ 256
#define LL   512
#define NAA  21
#define DD   128
#define EDIM (NAA*DD)   // 2688

// ---------------- scratch (static device globals; no allocation) ----------------
__device__ __align__(16) float g_w[LL*LL];               // full-precision sigmoid'd 512x512
__device__ __align__(16) float g_E[2*NSEQ][EDIM];        // E1 / E2
__device__ __align__(16) float g_S[2*NSEQ][NAA*NAA];     // per-seq 21x21 gram
__device__ __align__(16) float g_G1[(size_t)NSEQ*LL*NAA];    // G1[n1][l][c] = S1[n1, X1[n1,l], c]
__device__ __align__(16) float g_G2T[(size_t)LL*NAA*NSEQ];   // G2T[l][c][n2] = S2[n2, c, X2[n2,l]]
__device__ __align__(16) int   g_X1T[LL*NSEQ];               // X1T[l][n1]
__device__ __align__(16) int   g_X2T[LL*NSEQ];               // X2T[l][n2]
__device__ __align__(16) float g_d[2*NSEQ][LL];
__device__ __align__(16) float g_kpart[16*2*NSEQ];           // [jt][seq] partial d^T w d

// ---------------- helpers ----------------
__device__ __forceinline__ float to_tf32(float x) {
    float r; asm("cvt.rna.tf32.f32 %0, %1;" : "=f"(r) : "f"(x)); return r;
}
__device__ __forceinline__ void mma_tf32(float* d, const uint32_t* a, uint32_t b0, uint32_t b1) {
    asm volatile(
        "mma.sync.aligned.m16n8k8.row.col.f32.tf32.tf32.f32 "
        "{%0,%1,%2,%3}, {%4,%5,%6,%7}, {%8,%9}, {%0,%1,%2,%3};"
        : "+f"(d[0]), "+f"(d[1]), "+f"(d[2]), "+f"(d[3])
        : "r"(a[0]), "r"(a[1]), "r"(a[2]), "r"(a[3]), "r"(b0), "r"(b1));
}

// ---------------- w = sigmoid(symmetric(w_param)) ----------------
__global__ void k_build_w(const float* __restrict__ wp) {
    int idx = blockIdx.x*blockDim.x + threadIdx.x;
    if (idx >= LL*LL) return;
    int i = idx >> 9, j = idx & (LL-1);
    float v = 0.f;
    if (i > j)      v = wp[i*(i-1)/2 + j];
    else if (j > i) v = wp[j*(j-1)/2 + i];
    g_w[idx] = 1.f / (1.f + expf(-v));
}

// ---------------- transpose X ----------------
__global__ void k_XT(const int* __restrict__ X1, const int* __restrict__ X2) {
    int n = blockIdx.x & 255, set = blockIdx.x >> 8;
    const int* X = set ? (X2 + n*LL) : (X1 + n*LL);
    int* T = set ? g_X2T : g_X1T;
    for (int l = threadIdx.x; l < LL; l += 256) T[l*NSEQ + n] = X[l];
}

// ---------------- E: loop-flipped gather-sum (shares W rows across all seqs) ----------------
// grid (84 col-tiles of 32 floats, 2 seq-groups), 256 threads = 256 seqs.
__global__ void __launch_bounds__(256) k_Eg(const float* __restrict__ W, const float* __restrict__ b) {
    int col0 = blockIdx.x * 32;
    int sg   = blockIdx.y;
    const int* XT = sg ? g_X2T : g_X1T;
    __shared__ float sR[8*21*36];      // 8 l x 21 rows x 32 floats (pad 36)
    __shared__ int   sXc[8*256];
    int t = threadIdx.x;
    float4 acc[8];
    #pragma unroll
    for (int c = 0; c < 8; c++) acc[c] = ((const float4*)(b + col0))[c];
    for (int l0 = 0; l0 < LL; l0 += 8) {
        for (int f = t; f < 8*21*8; f += 256) {
            int row = f >> 3, c4 = f & 7;
            int l = row / 21, r = row - l*21;
            float4 v = ((const float4*)(W + (size_t)((l0+l)*NAA + r)*EDIM + col0))[c4];
            *(float4*)(sR + row*36 + c4*4) = v;
        }
        #pragma unroll
        for (int q = 0; q < 8; q++) sXc[q*256 + t] = XT[(l0+q)*NSEQ + t];
        __syncthreads();
        #pragma unroll
        for (int i = 0; i < 8; i++) {
            int x = sXc[i*256 + t];
            const float* base = sR + (i*21 + x)*36;
            #pragma unroll
            for (int c = 0; c < 8; c++) {
                float4 v = *(const float4*)(base + c*4);
                acc[c].x += v.x; acc[c].y += v.y; acc[c].z += v.z; acc[c].w += v.w;
            }
        }
        __syncthreads();
    }
    float* Er = g_E[sg*NSEQ + t] + col0;
    #pragma unroll
    for (int c = 0; c < 8; c++) ((float4*)Er)[c] = acc[c];
}

// ---------------- S[n,a,c] = E[n,a,:] . E[n,c,:] ----------------
__global__ void k_S() {
    int seq = blockIdx.x;
    __shared__ float sE[EDIM];
    for (int i = threadIdx.x; i < EDIM; i += blockDim.x) sE[i] = g_E[seq][i];
    __syncthreads();
    for (int e = threadIdx.x; e < NAA*NAA; e += blockDim.x) {
        int a = e / NAA, c = e - a*NAA;
        const float* pa = sE + a*DD;
        const float* pc = sE + c*DD;
        float s = 0.f;
        #pragma unroll 8
        for (int d = 0; d < DD; d++) s += pa[d]*pc[d];
        g_S[seq][e] = s;
    }
}

// ---------------- gather tables G1/G2T + diagonals d ----------------
__global__ void k_G(const int* __restrict__ X1, const int* __restrict__ X2) {
    int seq = blockIdx.x;
    __shared__ float sS[NAA*NAA];
    __shared__ int   sX[LL];
    const int* X = (seq < NSEQ) ? (X1 + seq*LL) : (X2 + (seq-NSEQ)*LL);
    for (int i = threadIdx.x; i < NAA*NAA; i += blockDim.x) sS[i] = g_S[seq][i];
    for (int i = threadIdx.x; i < LL; i += blockDim.x) sX[i] = X[i];
    __syncthreads();
    if (seq < NSEQ) {
        float* G = g_G1 + (size_t)seq*LL*NAA;
        for (int idx = threadIdx.x; idx < LL*NAA; idx += blockDim.x) {
            int l = idx / NAA, c = idx - l*NAA;
            G[idx] = sS[sX[l]*NAA + c];
        }
    } else {
        int n2 = seq - NSEQ;
        for (int idx = threadIdx.x; idx < LL*NAA; idx += blockDim.x) {
            int l = idx / NAA, c = idx - l*NAA;
            g_G2T[(size_t)idx*NSEQ + n2] = sS[c*NAA + sX[l]];
        }
    }
    for (int l = threadIdx.x; l < LL; l += blockDim.x)
        g_d[seq][l] = sS[sX[l]*NAA + sX[l]];
}

// ---------------- kpart[jt][s] = sum_{j in jt} d[s,j] * (w d)[s,j]  (fp32) ----------------
// grid (16 j-tiles of 32, 8 seq-groups of 64). 256 threads: sl = t>>2, jl = t&3.
__global__ void __launch_bounds__(256) k_quad() {
    extern __shared__ float qm[];
    float* sw  = qm;                 // [512 i][36]  (cols j of this jt)
    float* sDc = qm + 512*36;        // [64 s][132]
    int jt = blockIdx.x, sg = blockIdx.y;
    int t = threadIdx.x, sl = t >> 2, jl = t & 3;

    for (int f = t; f < 512*8; f += 256) {
        int i = f >> 3, c4 = f & 7;
        float4 v = *(const float4*)(g_w + (size_t)i*LL + jt*32 + c4*4);
        *(float4*)(sw + i*36 + c4*4) = v;
    }
    float y[8];
    #pragma unroll
    for (int k = 0; k < 8; k++) y[k] = 0.f;
    for (int ic = 0; ic < 4; ic++) {
        __syncthreads();
        for (int f = t; f < 64*32; f += 256) {
            int s = f >> 5, c4 = f & 31;
            float4 v = *(const float4*)(&g_d[sg*64 + s][ic*128 + c4*4]);
            *(float4*)(sDc + s*132 + c4*4) = v;
        }
        __syncthreads();
        #pragma unroll 4
        for (int i = 0; i < 128; i++) {
            float dv = sDc[sl*132 + i];
            const float* wr = sw + (ic*128 + i)*36 + jl;
            #pragma unroll
            for (int k = 0; k < 8; k++) y[k] += dv * wr[k*4];
        }
    }
    float pv = 0.f;
    #pragma unroll
    for (int k = 0; k < 8; k++)
        pv += y[k] * g_d[sg*64 + sl][jt*32 + jl + k*4];
    pv += __shfl_down_sync(0xffffffffu, pv, 2);
    pv += __shfl_down_sync(0xffffffffu, pv, 1);
    if (jl == 0) g_kpart[jt*512 + sg*64 + sl] = pv;
}

// ---------------- main: HMMA tf32 GEMM + fold ----------------
// Block = (n1, 64 n2-pairs). 256 threads = 8 warps: ph = warp&1 (32 pairs), jq = warp>>1 (32 j).
// subs^T built in smem (tf32-rounded); Y = subs @ w via mma.sync m16n8k8; fold inline.
__global__ void __launch_bounds__(256, 1)
k_mma(const int* __restrict__ X1, const float* __restrict__ ap, float* __restrict__ out) {
    extern __shared__ float sm[];
    float* sS  = sm;                       // [64 pairs][516 k]
    float* sW0 = sm + 64*516;              // [128 j][68 k]
    float* sW1 = sW0 + 128*68;
    float* sG1 = sW0;                      // phase-1 union (10752 f)
    int*   sX1 = (int*)(sW0 + LL*NAA);     // 512 ints
    float* sRed = sW0;                     // epilogue union (64*4 f)

    int tid  = threadIdx.x;
    int warp = tid >> 5, lane = tid & 31;
    int g = lane >> 2, t2 = lane & 3;
    int ph = warp & 1, jq = warp >> 1;
    int n1 = blockIdx.y;
    int n2base = blockIdx.x * 64;

    // ---- phase 1: stage G1[n1] + X1 row, then build subs^T (tf32) ----
    const float* G1p = g_G1 + (size_t)n1*LL*NAA;
    for (int i = tid; i < LL*NAA/4; i += 256)
        ((float4*)sG1)[i] = ((const float4*)G1p)[i];
    for (int i = tid; i < LL; i += 256) sX1[i] = X1[n1*LL + i];
    __syncthreads();
    {
        int p = tid & 63;
        int n2 = n2base + p;
        for (int l = tid >> 6; l < LL; l += 4) {
            int x2 = g_X2T[l*NSEQ + n2];
            int c  = sX1[l];
            float v = 0.5f*(sG1[l*NAA + x2] + g_G2T[(size_t)(l*NAA + c)*NSEQ + n2]);
            sS[p*516 + l] = to_tf32(v);
        }
    }
    __syncthreads();

    // ---- phase 2: Y = subs @ w, 4 j-tiles of 128, k-chunks of 64, double-buffered w ----
    float fr[2][2] = {{0.f,0.f},{0.f,0.f}};   // fold accumulators: [mt][row-half]
    int jr = tid >> 4, kq = tid & 15;          // w-chunk load mapping

    for (int jt = 0; jt < 4; jt++) {
        float acc[2][4][4];
        #pragma unroll
        for (int m = 0; m < 2; m++)
            #pragma unroll
            for (int n = 0; n < 4; n++)
                #pragma unroll
                for (int c = 0; c < 4; c++) acc[m][n][c] = 0.f;

        float4 pw[8];
        #pragma unroll
        for (int r = 0; r < 8; r++)
            pw[r] = *(const float4*)(g_w + (size_t)(jt*128 + jr + r*16)*LL + kq*4);
        __syncthreads();
        #pragma unroll
        for (int r = 0; r < 8; r++) {
            float4 v = pw[r];
            v.x = to_tf32(v.x); v.y = to_tf32(v.y); v.z = to_tf32(v.z); v.w = to_tf32(v.w);
            *(float4*)(sW0 + (jr + r*16)*68 + kq*4) = v;
        }
        __syncthreads();

        for (int kc = 0; kc < 8; kc++) {
            const float* wb = (kc & 1) ? sW1 : sW0;
            if (kc < 7) {
                #pragma unroll
                for (int r = 0; r < 8; r++)
                    pw[r] = *(const float4*)(g_w + (size_t)(jt*128 + jr + r*16)*LL + (kc+1)*64 + kq*4);
            }
            // 8 k-steps of mma
            #pragma unroll
            for (int ks = 0; ks < 8; ks++) {
                int ko = kc*64 + ks*8;
                uint32_t a[2][4];
                #pragma unroll
                for (int mt = 0; mt < 2; mt++) {
                    const float* ab = sS + (ph*32 + mt*16 + g)*516 + ko + t2;
                    a[mt][0] = __float_as_uint(ab[0]);
                    a[mt][1] = __float_as_uint(ab[8*516]);
                    a[mt][2] = __float_as_uint(ab[4]);
                    a[mt][3] = __float_as_uint(ab[8*516 + 4]);
                }
                #pragma unroll
                for (int nt = 0; nt < 4; nt++) {
                    const float* bb = wb + (jq*32 + nt*8 + g)*68 + ks*8 + t2;
                    uint32_t b0 = __float_as_uint(bb[0]);
                    uint32_t b1 = __float_as_uint(bb[4]);
                    mma_tf32(acc[0][nt], a[0], b0, b1);
                    mma_tf32(acc[1][nt], a[1], b0, b1);
                }
            }
            if (kc < 7) {
                __syncthreads();
                float* dst = (kc & 1) ? sW0 : sW1;
                #pragma unroll
                for (int r = 0; r < 8; r++) {
                    float4 v = pw[r];
                    v.x = to_tf32(v.x); v.y = to_tf32(v.y); v.z = to_tf32(v.z); v.w = to_tf32(v.w);
                    *(float4*)(dst + (jr + r*16)*68 + kq*4) = v;
                }
                __syncthreads();
            }
        }
        // fold this jt: fr[mt][h] += Y[row, j] * subs[row, j]
        #pragma unroll
        for (int mt = 0; mt < 2; mt++) {
            const float* s0 = sS + (ph*32 + mt*16 + g)*516;
            const float* s8 = s0 + 8*516;
            #pragma unroll
            for (int nt = 0; nt < 4; nt++) {
                int j = jt*128 + jq*32 + nt*8 + 2*t2;
                fr[mt][0] += acc[mt][nt][0]*s0[j] + acc[mt][nt][1]*s0[j+1];
                fr[mt][1] += acc[mt][nt][2]*s8[j] + acc[mt][nt][3]*s8[j+1];
            }
        }
    }
    __syncthreads();   // all warps done with sW1 before sRed (aliases sW0) writes? sRed=sW0; safe: last mma read sW1; sync anyway.

    // reduce quads, stash per-jq partials
    #pragma unroll
    for (int mt = 0; mt < 2; mt++)
        #pragma unroll
        for (int h = 0; h < 2; h++) {
            float v = fr[mt][h];
            v += __shfl_down_sync(0xffffffffu, v, 2);
            v += __shfl_down_sync(0xffffffffu, v, 1);
            if (t2 == 0) sRed[(ph*32 + mt*16 + h*8 + g)*4 + jq] = v;
        }
    __syncthreads();
    if (tid < 64) {
        float kv = sRed[tid*4+0] + sRed[tid*4+1] + sRed[tid*4+2] + sRed[tid*4+3];
        float s1 = 0.f, s2 = 0.f;
        #pragma unroll
        for (int q = 0; q < 16; q++) {
            s1 += g_kpart[q*512 + n1];
            s2 += g_kpart[q*512 + NSEQ + n2base + tid];
        }
        float a0 = ap[0];
        out[n1*NSEQ + n2base + tid] = a0*a0 * kv * rsqrtf(s1) * rsqrtf(s2);
    }
}

// ---------------- launch ----------------
extern "C" void kernel_launch(void* const* d_in, const int* in_sizes, int n_in,
                              void* d_out, int out_size) {
    const int*   X1 = (const int*)d_in[0];
    const int*   X2 = (const int*)d_in[1];
    const float* W  = (const float*)d_in[2];
    const float* b  = (const float*)d_in[3];
    const float* wp = (const float*)d_in[4];
    const float* a  = (const float*)d_in[5];
    float* out = (float*)d_out;

    const int SMEM_MMA  = (64*516 + 2*128*68) * 4;      // 201728 B
    const int SMEM_QUAD = (512*36 + 64*132) * 4;        // 107520 B
    cudaFuncSetAttribute(k_mma,  cudaFuncAttributeMaxDynamicSharedMemorySize, SMEM_MMA);
    cudaFuncSetAttribute(k_quad, cudaFuncAttributeMaxDynamicSharedMemorySize, SMEM_QUAD);

    k_build_w<<<(LL*LL + 255)/256, 256>>>(wp);
    k_XT<<<2*NSEQ, 256>>>(X1, X2);
    k_Eg<<<dim3(84, 2), 256>>>(W, b);
    k_S<<<2*NSEQ, 256>>>();
    k_G<<<2*NSEQ, 256>>>(X1, X2);
    k_quad<<<dim3(16, 8), 256, SMEM_QUAD>>>();
    k_mma<<<dim3(4, 256), 256, SMEM_MMA>>>(X1, a, out);
}

// round 4
// speedup vs baseline: 1.5342x; 1.0992x over previous
#include <cuda_runtime.h>
#include <math.h>
#include <cstdint>

#define NSEQ 256
#define LL   512
#define NAA  21
#define DD   128
#define EDIM (NAA*DD)   // 2688

// ---------------- scratch (static device globals; no allocation) ----------------
__device__ __align__(16) float g_w[LL*LL];               // tf32-rounded sigmoid'd 512x512
__device__ __align__(16) float g_E[2*NSEQ][EDIM];        // E1 / E2
__device__ __align__(16) float g_G1[(size_t)NSEQ*LL*NAA];    // G1[n1][l][c] = S1[n1, X1[n1,l], c]
__device__ __align__(16) float g_G2T[(size_t)LL*NAA*NSEQ];   // G2T[l][c][n2] = S2[n2, c, X2[n2,l]]
__device__ __align__(16) int   g_X1T[LL*NSEQ];               // X1T[l][n1]
__device__ __align__(16) int   g_X2T[LL*NSEQ];               // X2T[l][n2]
__device__ __align__(16) float g_d[2*NSEQ][LL];
__device__ __align__(16) float g_kpart[16*2*NSEQ];           // [jt][seq] partial d^T w d
__device__ __align__(16) float g_Kraw[NSEQ*NSEQ];            // unnormalized quadratic forms

// ---------------- helpers ----------------
__device__ __forceinline__ float to_tf32(float x) {
    float r; asm("cvt.rna.tf32.f32 %0, %1;" : "=f"(r) : "f"(x)); return r;
}
__device__ __forceinline__ void mma_tf32(float* d, const uint32_t* a, uint32_t b0, uint32_t b1) {
    asm volatile(
        "mma.sync.aligned.m16n8k8.row.col.f32.tf32.tf32.f32 "
        "{%0,%1,%2,%3}, {%4,%5,%6,%7}, {%8,%9}, {%0,%1,%2,%3};"
        : "+f"(d[0]), "+f"(d[1]), "+f"(d[2]), "+f"(d[3])
        : "r"(a[0]), "r"(a[1]), "r"(a[2]), "r"(a[3]), "r"(b0), "r"(b1));
}
__device__ __forceinline__ uint32_t smem_u32(const void* p) {
    uint32_t a;
    asm("{ .reg .u64 t; cvta.to.shared.u64 t, %1; cvt.u32.u64 %0, t; }" : "=r"(a) : "l"(p));
    return a;
}
__device__ __forceinline__ void cp16(uint32_t dst, const void* src) {
    asm volatile("cp.async.cg.shared.global [%0], [%1], 16;" :: "r"(dst), "l"(src));
}
#define CP_COMMIT() asm volatile("cp.async.commit_group;" ::: "memory")
#define CP_WAIT0()  asm volatile("cp.async.wait_group 0;" ::: "memory")
#define CP_WAIT1()  asm volatile("cp.async.wait_group 1;" ::: "memory")

// ---------------- launch 1: w = tf32(sigmoid(sym(w_param))) + X transposes ----------------
__global__ void k_init(const float* __restrict__ wp,
                       const int* __restrict__ X1, const int* __restrict__ X2) {
    int bid = blockIdx.x;
    if (bid < 1024) {
        int idx = bid*256 + threadIdx.x;
        int i = idx >> 9, j = idx & (LL-1);
        float v = 0.f;
        if (i > j)      v = wp[i*(i-1)/2 + j];
        else if (j > i) v = wp[j*(j-1)/2 + i];
        g_w[idx] = to_tf32(1.f / (1.f + expf(-v)));
    } else {
        int q = bid - 1024;            // 0..511
        int n = q & 255, set = q >> 8;
        const int* X = set ? (X2 + n*LL) : (X1 + n*LL);
        int* T = set ? g_X2T : g_X1T;
        for (int l = threadIdx.x; l < LL; l += 256) T[l*NSEQ + n] = X[l];
    }
}

// ---------------- launch 2: E gather-sum, loop-flipped over l ----------------
__global__ void __launch_bounds__(256) k_Eg(const float* __restrict__ W, const float* __restrict__ b) {
    int col0 = blockIdx.x * 32;
    int sg   = blockIdx.y;
    const int* XT = sg ? g_X2T : g_X1T;
    __shared__ float sR[8*21*36];
    __shared__ int   sXc[8*256];
    int t = threadIdx.x;
    float4 acc[8];
    #pragma unroll
    for (int c = 0; c < 8; c++) acc[c] = ((const float4*)(b + col0))[c];
    for (int l0 = 0; l0 < LL; l0 += 8) {
        for (int f = t; f < 8*21*8; f += 256) {
            int row = f >> 3, c4 = f & 7;
            int l = row / 21, r = row - l*21;
            float4 v = ((const float4*)(W + (size_t)((l0+l)*NAA + r)*EDIM + col0))[c4];
            *(float4*)(sR + row*36 + c4*4) = v;
        }
        #pragma unroll
        for (int q = 0; q < 8; q++) sXc[q*256 + t] = XT[(l0+q)*NSEQ + t];
        __syncthreads();
        #pragma unroll
        for (int i = 0; i < 8; i++) {
            int x = sXc[i*256 + t];
            const float* base = sR + (i*21 + x)*36;
            #pragma unroll
            for (int c = 0; c < 8; c++) {
                float4 v = *(const float4*)(base + c*4);
                acc[c].x += v.x; acc[c].y += v.y; acc[c].z += v.z; acc[c].w += v.w;
            }
        }
        __syncthreads();
    }
    float* Er = g_E[sg*NSEQ + t] + col0;
    #pragma unroll
    for (int c = 0; c < 8; c++) ((float4*)Er)[c] = acc[c];
}

// ---------------- launch 3: fused S (warp-per-pair) + gather tables + diag ----------------
__global__ void __launch_bounds__(256) k_SG(const int* __restrict__ X1, const int* __restrict__ X2) {
    int seq = blockIdx.x;
    __shared__ float sE[EDIM];
    __shared__ float sS[NAA*NAA];
    __shared__ int   sX[LL];
    int tid = threadIdx.x, warp = tid >> 5, lane = tid & 31;
    const int* X = (seq < NSEQ) ? (X1 + seq*LL) : (X2 + (seq-NSEQ)*LL);
    for (int i = tid; i < EDIM/4; i += 256) ((float4*)sE)[i] = ((const float4*)g_E[seq])[i];
    for (int i = tid; i < LL; i += 256) sX[i] = X[i];
    __syncthreads();
    // S[a,c] via warp-per-pair: lane owns 4 dims, conflict-free float4 LDS
    for (int e = warp; e < NAA*NAA; e += 8) {
        int a = e / NAA, c = e - a*NAA;
        float4 pa = *(const float4*)(sE + a*DD + lane*4);
        float4 pc = *(const float4*)(sE + c*DD + lane*4);
        float s = pa.x*pc.x + pa.y*pc.y + pa.z*pc.z + pa.w*pc.w;
        #pragma unroll
        for (int o = 16; o; o >>= 1) s += __shfl_xor_sync(0xffffffffu, s, o);
        if (lane == 0) sS[e] = s;
    }
    __syncthreads();
    if (seq < NSEQ) {
        float* G = g_G1 + (size_t)seq*LL*NAA;
        for (int idx = tid; idx < LL*NAA; idx += 256) {
            int l = idx / NAA, c = idx - l*NAA;
            G[idx] = sS[sX[l]*NAA + c];
        }
    } else {
        int n2 = seq - NSEQ;
        for (int idx = tid; idx < LL*NAA; idx += 256) {
            int l = idx / NAA, c = idx - l*NAA;
            g_G2T[(size_t)idx*NSEQ + n2] = sS[c*NAA + sX[l]];
        }
    }
    for (int l = tid; l < LL; l += 256)
        g_d[seq][l] = sS[sX[l]*NAA + sX[l]];
}

// ---------------- launch 4: HMMA tf32 GEMM + fold (unnormalized) ----------------
// Block = (n1, 64 n2-pairs). 8 warps: ph = warp&1 (32 pairs), jq = warp>>1 (32 j).
__global__ void __launch_bounds__(256, 1)
k_mma(const int* __restrict__ X1, float* __restrict__ kraw) {
    extern __shared__ float sm[];
    float* sS  = sm;                       // [64 pairs][516 k]
    float* sW0 = sm + 64*516;              // [128 j][68 k]
    float* sW1 = sW0 + 128*68;
    float* sG1 = sW0;                      // phase-1 union
    int*   sX1 = (int*)(sW0 + LL*NAA);
    float* sRed = sW0;                     // epilogue union

    int tid  = threadIdx.x;
    int warp = tid >> 5, lane = tid & 31;
    int g = lane >> 2, t2 = lane & 3;
    int ph = warp & 1, jq = warp >> 1;
    int n1 = blockIdx.y;
    int n2base = blockIdx.x * 64;

    // ---- phase 1: stage G1[n1] + X1 row, build subs^T (tf32) ----
    const float* G1p = g_G1 + (size_t)n1*LL*NAA;
    for (int i = tid; i < LL*NAA/4; i += 256)
        ((float4*)sG1)[i] = ((const float4*)G1p)[i];
    for (int i = tid; i < LL; i += 256) sX1[i] = X1[n1*LL + i];
    __syncthreads();
    {
        int p = tid & 63;
        int n2 = n2base + p;
        for (int l = tid >> 6; l < LL; l += 4) {
            int x2 = g_X2T[l*NSEQ + n2];
            int c  = sX1[l];
            float v = 0.5f*(sG1[l*NAA + x2] + g_G2T[(size_t)(l*NAA + c)*NSEQ + n2]);
            sS[p*516 + l] = to_tf32(v);
        }
    }
    __syncthreads();

    // ---- phase 2: Y = subs @ w via mma.sync, w staged by cp.async double-buffer ----
    float fr[2][2] = {{0.f,0.f},{0.f,0.f}};
    int jr = tid >> 4, kq = tid & 15;
    uint32_t swb[2] = { smem_u32(sW0), smem_u32(sW1) };

    for (int jt = 0; jt < 4; jt++) {
        float acc[2][4][4];
        #pragma unroll
        for (int m = 0; m < 2; m++)
            #pragma unroll
            for (int n = 0; n < 4; n++)
                #pragma unroll
                for (int c = 0; c < 4; c++) acc[m][n][c] = 0.f;

        // prologue: stage kc=0 into buf0
        #pragma unroll
        for (int r = 0; r < 8; r++)
            cp16(swb[0] + (uint32_t)(((jr + r*16)*68 + kq*4)*4),
                 g_w + (size_t)(jt*128 + jr + r*16)*LL + kq*4);
        CP_COMMIT();

        for (int kc = 0; kc < 8; kc++) {
            if (kc < 7) {
                uint32_t dstb = swb[(kc+1) & 1];
                #pragma unroll
                for (int r = 0; r < 8; r++)
                    cp16(dstb + (uint32_t)(((jr + r*16)*68 + kq*4)*4),
                         g_w + (size_t)(jt*128 + jr + r*16)*LL + (kc+1)*64 + kq*4);
                CP_COMMIT();
                CP_WAIT1();
            } else {
                CP_WAIT0();
            }
            __syncthreads();
            const float* wb = (kc & 1) ? sW1 : sW0;
            #pragma unroll
            for (int ks = 0; ks < 8; ks++) {
                int ko = kc*64 + ks*8;
                uint32_t a[2][4];
                #pragma unroll
                for (int mt = 0; mt < 2; mt++) {
                    const float* ab = sS + (ph*32 + mt*16 + g)*516 + ko + t2;
                    a[mt][0] = __float_as_uint(ab[0]);
                    a[mt][1] = __float_as_uint(ab[8*516]);
                    a[mt][2] = __float_as_uint(ab[4]);
                    a[mt][3] = __float_as_uint(ab[8*516 + 4]);
                }
                #pragma unroll
                for (int nt = 0; nt < 4; nt++) {
                    const float* bb = wb + (jq*32 + nt*8 + g)*68 + ks*8 + t2;
                    uint32_t b0 = __float_as_uint(bb[0]);
                    uint32_t b1 = __float_as_uint(bb[4]);
                    mma_tf32(acc[0][nt], a[0], b0, b1);
                    mma_tf32(acc[1][nt], a[1], b0, b1);
                }
            }
            __syncthreads();   // all warps done reading wb before it is re-staged
        }
        // fold this jt
        #pragma unroll
        for (int mt = 0; mt < 2; mt++) {
            const float* s0 = sS + (ph*32 + mt*16 + g)*516;
            const float* s8 = s0 + 8*516;
            #pragma unroll
            for (int nt = 0; nt < 4; nt++) {
                int j = jt*128 + jq*32 + nt*8 + 2*t2;
                fr[mt][0] += acc[mt][nt][0]*s0[j] + acc[mt][nt][1]*s0[j+1];
                fr[mt][1] += acc[mt][nt][2]*s8[j] + acc[mt][nt][3]*s8[j+1];
            }
        }
    }
    __syncthreads();

    #pragma unroll
    for (int mt = 0; mt < 2; mt++)
        #pragma unroll
        for (int h = 0; h < 2; h++) {
            float v = fr[mt][h];
            v += __shfl_down_sync(0xffffffffu, v, 2);
            v += __shfl_down_sync(0xffffffffu, v, 1);
            if (t2 == 0) sRed[(ph*32 + mt*16 + h*8 + g)*4 + jq] = v;
        }
    __syncthreads();
    if (tid < 64)
        kraw[n1*NSEQ + n2base + tid] =
            sRed[tid*4+0] + sRed[tid*4+1] + sRed[tid*4+2] + sRed[tid*4+3];
}

// ---------------- launch 5: kpart[jt][s] partial d^T w d ----------------
__global__ void __launch_bounds__(256) k_quad() {
    extern __shared__ float qm[];
    float* sw  = qm;                 // [512 i][36]
    float* sDc = qm + 512*36;        // [64 s][132]
    int jt = blockIdx.x, sg = blockIdx.y;
    int t = threadIdx.x, sl = t >> 2, jl = t & 3;

    for (int f = t; f < 512*8; f += 256) {
        int i = f >> 3, c4 = f & 7;
        float4 v = *(const float4*)(g_w + (size_t)i*LL + jt*32 + c4*4);
        *(float4*)(sw + i*36 + c4*4) = v;
    }
    float y[8];
    #pragma unroll
    for (int k = 0; k < 8; k++) y[k] = 0.f;
    for (int ic = 0; ic < 4; ic++) {
        __syncthreads();
        for (int f = t; f < 64*32; f += 256) {
            int s = f >> 5, c4 = f & 31;
            float4 v = *(const float4*)(&g_d[sg*64 + s][ic*128 + c4*4]);
            *(float4*)(sDc + s*132 + c4*4) = v;
        }
        __syncthreads();
        #pragma unroll 4
        for (int i = 0; i < 128; i++) {
            float dv = sDc[sl*132 + i];
            const float* wr = sw + (ic*128 + i)*36 + jl;
            #pragma unroll
            for (int k = 0; k < 8; k++) y[k] += dv * wr[k*4];
        }
    }
    float pv = 0.f;
    #pragma unroll
    for (int k = 0; k < 8; k++)
        pv += y[k] * g_d[sg*64 + sl][jt*32 + jl + k*4];
    pv += __shfl_down_sync(0xffffffffu, pv, 2);
    pv += __shfl_down_sync(0xffffffffu, pv, 1);
    if (jl == 0) g_kpart[jt*512 + sg*64 + sl] = pv;
}

// ---------------- launch 6: normalize ----------------
__global__ void k_fin(const float* __restrict__ ap, float* __restrict__ out) {
    int n1 = blockIdx.x, n2 = threadIdx.x;
    float s1 = 0.f, s2 = 0.f;
    #pragma unroll
    for (int q = 0; q < 16; q++) {
        s1 += g_kpart[q*512 + n1];
        s2 += g_kpart[q*512 + NSEQ + n2];
    }
    float a0 = ap[0];
    out[n1*NSEQ + n2] = a0*a0 * g_Kraw[n1*NSEQ + n2] * rsqrtf(s1) * rsqrtf(s2);
}

// ---------------- launch ----------------
extern "C" void kernel_launch(void* const* d_in, const int* in_sizes, int n_in,
                              void* d_out, int out_size) {
    const int*   X1 = (const int*)d_in[0];
    const int*   X2 = (const int*)d_in[1];
    const float* W  = (const float*)d_in[2];
    const float* b  = (const float*)d_in[3];
    const float* wp = (const float*)d_in[4];
    const float* a  = (const float*)d_in[5];
    float* out = (float*)d_out;

    float* kraw;  cudaGetSymbolAddress((void**)&kraw, g_Kraw);

    const int SMEM_MMA  = (64*516 + 2*128*68) * 4;      // 201728 B
    const int SMEM_QUAD = (512*36 + 64*132) * 4;        // 107520 B
    cudaFuncSetAttribute(k_mma,  cudaFuncAttributeMaxDynamicSharedMemorySize, SMEM_MMA);
    cudaFuncSetAttribute(k_quad, cudaFuncAttributeMaxDynamicSharedMemorySize, SMEM_QUAD);

    k_init<<<1024 + 512, 256>>>(wp, X1, X2);
    k_Eg<<<dim3(84, 2), 256>>>(W, b);
    k_SG<<<2*NSEQ, 256>>>(X1, X2);
    k_mma<<<dim3(4, 256), 256, SMEM_MMA>>>(X1, kraw);
    k_quad<<<dim3(16, 8), 256, SMEM_QUAD>>>();
    k_fin<<<NSEQ, NSEQ>>>(a, out);
}

// round 6
// speedup vs baseline: 1.6043x; 1.0457x over previous
#include <cuda_runtime.h>
#include <math.h>
#include <cstdint>

#define NSEQ 256
#define LL   512
#define NAA  21
#define DD   128
#define EDIM (NAA*DD)   // 2688

// ---------------- scratch (static device globals; no allocation) ----------------
__device__ __align__(16) float g_w[LL*LL];               // tf32-rounded sigmoid'd 512x512
__device__ __align__(16) float g_E[2*NSEQ][EDIM];        // E1 / E2
__device__ __align__(16) float g_G1[(size_t)NSEQ*LL*NAA];    // G1[n1][l][c] = S1[n1, X1[n1,l], c]
__device__ __align__(16) float g_G2T[(size_t)LL*NAA*NSEQ];   // G2T[l][c][n2] = S2[n2, c, X2[n2,l]]
__device__ __align__(16) int   g_X1T[LL*NSEQ];
__device__ __align__(16) int   g_X2T[LL*NSEQ];
__device__ __align__(16) float g_d[2*NSEQ][LL];
__device__ __align__(16) float g_kpart[16*2*NSEQ];
__device__ __align__(16) float g_Kraw[NSEQ*NSEQ];

// ---------------- helpers ----------------
__device__ __forceinline__ float to_tf32(float x) {
    float r; asm("cvt.rna.tf32.f32 %0, %1;" : "=f"(r) : "f"(x)); return r;
}
__device__ __forceinline__ void mma_tf32(float* d, const uint32_t* a, uint32_t b0, uint32_t b1) {
    asm volatile(
        "mma.sync.aligned.m16n8k8.row.col.f32.tf32.tf32.f32 "
        "{%0,%1,%2,%3}, {%4,%5,%6,%7}, {%8,%9}, {%0,%1,%2,%3};"
        : "+f"(d[0]), "+f"(d[1]), "+f"(d[2]), "+f"(d[3])
        : "r"(a[0]), "r"(a[1]), "r"(a[2]), "r"(a[3]), "r"(b0), "r"(b1));
}
__device__ __forceinline__ uint32_t smem_u32(const void* p) {
    uint32_t a;
    asm("{ .reg .u64 t; cvta.to.shared.u64 t, %1; cvt.u32.u64 %0, t; }" : "=r"(a) : "l"(p));
    return a;
}
__device__ __forceinline__ void cp16(uint32_t dst, const void* src) {
    asm volatile("cp.async.cg.shared.global [%0], [%1], 16;" :: "r"(dst), "l"(src));
}
#define CP_COMMIT() asm volatile("cp.async.commit_group;" ::: "memory")
#define CP_WAIT0()  asm volatile("cp.async.wait_group 0;" ::: "memory")
#define CP_WAIT1()  asm volatile("cp.async.wait_group 1;" ::: "memory")

// ---------------- launch 1: w = tf32(sigmoid(sym(w_param))) + X transposes ----------------
__global__ void k_init(const float* __restrict__ wp,
                       const int* __restrict__ X1, const int* __restrict__ X2) {
    int bid = blockIdx.x;
    if (bid < 1024) {
        int idx = bid*256 + threadIdx.x;
        int i = idx >> 9, j = idx & (LL-1);
        float v = 0.f;
        if (i > j)      v = wp[i*(i-1)/2 + j];
        else if (j > i) v = wp[j*(j-1)/2 + i];
        g_w[idx] = to_tf32(1.f / (1.f + expf(-v)));
    } else {
        int q = bid - 1024;
        int n = q & 255, set = q >> 8;
        const int* X = set ? (X2 + n*LL) : (X1 + n*LL);
        int* T = set ? g_X2T : g_X1T;
        for (int l = threadIdx.x; l < LL; l += 256) T[l*NSEQ + n] = X[l];
    }
}

// ---------------- launch 2: E gather-sum, conflict-free stride-35 smem ----------------
__global__ void __launch_bounds__(256) k_Eg(const float* __restrict__ W, const float* __restrict__ b) {
    int col0 = blockIdx.x * 32;
    int sg   = blockIdx.y;
    const int* XT = sg ? g_X2T : g_X1T;
    __shared__ float sR[168*35];       // 8 l x 21 rows x 32 cols, stride 35 (3*x injective mod 32)
    __shared__ int   sXc[8*256];
    int t = threadIdx.x;
    float acc[32];
    #pragma unroll
    for (int c = 0; c < 32; c++) acc[c] = b[col0 + c];
    for (int l0 = 0; l0 < LL; l0 += 8) {
        __syncthreads();
        for (int f = t; f < 168*32; f += 256) {
            int row = f >> 5, c = f & 31;
            int l = row / 21, r = row - l*21;
            sR[row*35 + c] = W[(size_t)((l0+l)*NAA + r)*EDIM + col0 + c];
        }
        #pragma unroll
        for (int q = 0; q < 8; q++) sXc[q*256 + t] = XT[(l0+q)*NSEQ + t];
        __syncthreads();
        #pragma unroll
        for (int i = 0; i < 8; i++) {
            const float* base = sR + (i*21 + sXc[i*256 + t])*35;
            #pragma unroll
            for (int c = 0; c < 32; c++) acc[c] += base[c];
        }
    }
    float* Er = g_E[sg*NSEQ + t] + col0;
    #pragma unroll
    for (int c = 0; c < 8; c++)
        ((float4*)Er)[c] = make_float4(acc[4*c], acc[4*c+1], acc[4*c+2], acc[4*c+3]);
}

// ---------------- launch 3: fused S (warp-per-pair) + gather tables + diag ----------------
__global__ void __launch_bounds__(256) k_SG(const int* __restrict__ X1, const int* __restrict__ X2) {
    int seq = blockIdx.x;
    __shared__ float sE[EDIM];
    __shared__ float sS[NAA*NAA];
    __shared__ int   sX[LL];
    int tid = threadIdx.x, warp = tid >> 5, lane = tid & 31;
    const int* X = (seq < NSEQ) ? (X1 + seq*LL) : (X2 + (seq-NSEQ)*LL);
    for (int i = tid; i < EDIM/4; i += 256) ((float4*)sE)[i] = ((const float4*)g_E[seq])[i];
    for (int i = tid; i < LL; i += 256) sX[i] = X[i];
    __syncthreads();
    for (int e = warp; e < NAA*NAA; e += 8) {
        int a = e / NAA, c = e - a*NAA;
        float4 pa = *(const float4*)(sE + a*DD + lane*4);
        float4 pc = *(const float4*)(sE + c*DD + lane*4);
        float s = pa.x*pc.x + pa.y*pc.y + pa.z*pc.z + pa.w*pc.w;
        #pragma unroll
        for (int o = 16; o; o >>= 1) s += __shfl_xor_sync(0xffffffffu, s, o);
        if (lane == 0) sS[e] = s;
    }
    __syncthreads();
    if (seq < NSEQ) {
        float* G = g_G1 + (size_t)seq*LL*NAA;
        for (int idx = tid; idx < LL*NAA; idx += 256) {
            int l = idx / NAA, c = idx - l*NAA;
            G[idx] = sS[sX[l]*NAA + c];
        }
    } else {
        int n2 = seq - NSEQ;
        for (int idx = tid; idx < LL*NAA; idx += 256) {
            int l = idx / NAA, c = idx - l*NAA;
            g_G2T[(size_t)idx*NSEQ + n2] = sS[c*NAA + sX[l]];
        }
    }
    for (int l = tid; l < LL; l += 256)
        g_d[seq][l] = sS[sX[l]*NAA + sX[l]];
}

// ---------------- launch 4: HMMA tf32 GEMM + fold, 512 threads / 16 warps ----------------
// Block = (n1, 64 n2). 16 warps: ph = warp&1 (m-half 32), jq = warp>>1 (16 j of 128-j tile).
__global__ void __launch_bounds__(512, 1)
k_mma(const int* __restrict__ X1, float* __restrict__ kraw) {
    extern __shared__ float sm[];
    float* sS  = sm;                       // [64 pairs][516 k]
    float* sW0 = sm + 64*516;              // [128 j][68 k]
    float* sW1 = sW0 + 128*68;
    float* sG1 = sW0;                      // phase-1 union
    int*   sX1 = (int*)(sW0 + LL*NAA);
    float* sRed = sW0;                     // epilogue union (64 rows x 8 jq)

    int tid  = threadIdx.x;
    int warp = tid >> 5, lane = tid & 31;
    int g = lane >> 2, t2 = lane & 3;
    int ph = warp & 1, jq = warp >> 1;     // jq 0..7
    int n1 = blockIdx.y;
    int n2base = blockIdx.x * 64;

    // ---- phase 1: stage G1[n1] + X1 row, build subs^T (tf32) ----
    const float* G1p = g_G1 + (size_t)n1*LL*NAA;
    for (int i = tid; i < LL*NAA/4; i += 512)
        ((float4*)sG1)[i] = ((const float4*)G1p)[i];
    for (int i = tid; i < LL; i += 512) sX1[i] = X1[n1*LL + i];
    __syncthreads();
    {
        int p = tid & 63;
        int n2 = n2base + p;
        for (int l = tid >> 6; l < LL; l += 8) {
            int x2 = g_X2T[l*NSEQ + n2];
            int c  = sX1[l];
            float v = 0.5f*(sG1[l*NAA + x2] + g_G2T[(size_t)(l*NAA + c)*NSEQ + n2]);
            sS[p*516 + l] = to_tf32(v);
        }
    }
    __syncthreads();

    // ---- phase 2: Y = subs @ w via mma.sync, w staged by cp.async double-buffer ----
    float fr[2][2] = {{0.f,0.f},{0.f,0.f}};
    uint32_t swb[2] = { smem_u32(sW0), smem_u32(sW1) };

    for (int jt = 0; jt < 4; jt++) {
        float acc[2][2][4];
        #pragma unroll
        for (int m = 0; m < 2; m++)
            #pragma unroll
            for (int n = 0; n < 2; n++)
                #pragma unroll
                for (int c = 0; c < 4; c++) acc[m][n][c] = 0.f;

        // prologue: stage kc=0 into buf0 (128 rows x 64 floats, stride 68)
        #pragma unroll
        for (int q = 0; q < 4; q++) {
            int idx = tid + q*512;            // float4 idx 0..2047
            int row = idx >> 4, c16 = idx & 15;
            cp16(swb[0] + (uint32_t)(row*272 + c16*16),
                 g_w + (size_t)(jt*128 + row)*LL + c16*4);
        }
        CP_COMMIT();

        for (int kc = 0; kc < 8; kc++) {
            if (kc < 7) {
                uint32_t dstb = swb[(kc+1) & 1];
                #pragma unroll
                for (int q = 0; q < 4; q++) {
                    int idx = tid + q*512;
                    int row = idx >> 4, c16 = idx & 15;
                    cp16(dstb + (uint32_t)(row*272 + c16*16),
                         g_w + (size_t)(jt*128 + row)*LL + (kc+1)*64 + c16*4);
                }
                CP_COMMIT();
                CP_WAIT1();
            } else {
                CP_WAIT0();
            }
            __syncthreads();
            const float* wb = (kc & 1) ? sW1 : sW0;
            #pragma unroll
            for (int ks = 0; ks < 8; ks++) {
                int ko = kc*64 + ks*8;
                uint32_t a[2][4];
                #pragma unroll
                for (int mt = 0; mt < 2; mt++) {
                    const float* ab = sS + (ph*32 + mt*16 + g)*516 + ko + t2;
                    a[mt][0] = __float_as_uint(ab[0]);
                    a[mt][1] = __float_as_uint(ab[8*516]);
                    a[mt][2] = __float_as_uint(ab[4]);
                    a[mt][3] = __float_as_uint(ab[8*516 + 4]);
                }
                #pragma unroll
                for (int nt = 0; nt < 2; nt++) {
                    const float* bb = wb + (jq*16 + nt*8 + g)*68 + ks*8 + t2;
                    uint32_t b0 = __float_as_uint(bb[0]);
                    uint32_t b1 = __float_as_uint(bb[4]);
                    mma_tf32(acc[0][nt], a[0], b0, b1);
                    mma_tf32(acc[1][nt], a[1], b0, b1);
                }
            }
            __syncthreads();   // all warps done reading wb before re-staging
        }
        // fold this jt
        #pragma unroll
        for (int mt = 0; mt < 2; mt++) {
            const float* s0 = sS + (ph*32 + mt*16 + g)*516;
            const float* s8 = s0 + 8*516;
            #pragma unroll
            for (int nt = 0; nt < 2; nt++) {
                int j = jt*128 + jq*16 + nt*8 + 2*t2;
                fr[mt][0] += acc[mt][nt][0]*s0[j] + acc[mt][nt][1]*s0[j+1];
                fr[mt][1] += acc[mt][nt][2]*s8[j] + acc[mt][nt][3]*s8[j+1];
            }
        }
    }
    __syncthreads();

    #pragma unroll
    for (int mt = 0; mt < 2; mt++)
        #pragma unroll
        for (int h = 0; h < 2; h++) {
            float v = fr[mt][h];
            v += __shfl_down_sync(0xffffffffu, v, 2);
            v += __shfl_down_sync(0xffffffffu, v, 1);
            if (t2 == 0) sRed[(ph*32 + mt*16 + h*8 + g)*8 + jq] = v;
        }
    __syncthreads();
    if (tid < 64) {
        float s = 0.f;
        #pragma unroll
        for (int q = 0; q < 8; q++) s += sRed[tid*8 + q];
        kraw[n1*NSEQ + n2base + tid] = s;
    }
}

// ---------------- launch 5: kpart[jt][s] partial d^T w d ----------------
__global__ void __launch_bounds__(256) k_quad() {
    extern __shared__ float qm[];
    float* sw  = qm;                 // [512 i][36]
    float* sDc = qm + 512*36;        // [64 s][132]
    int jt = blockIdx.x, sg = blockIdx.y;
    int t = threadIdx.x, sl = t >> 2, jl = t & 3;

    for (int f = t; f < 512*8; f += 256) {
        int i = f >> 3, c4 = f & 7;
        float4 v = *(const float4*)(g_w + (size_t)i*LL + jt*32 + c4*4);
        *(float4*)(sw + i*36 + c4*4) = v;
    }
    float y[8];
    #pragma unroll
    for (int k = 0; k < 8; k++) y[k] = 0.f;
    for (int ic = 0; ic < 4; ic++) {
        __syncthreads();
        for (int f = t; f < 64*32; f += 256) {
            int s = f >> 5, c4 = f & 31;
            float4 v = *(const float4*)(&g_d[sg*64 + s][ic*128 + c4*4]);
            *(float4*)(sDc + s*132 + c4*4) = v;
        }
        __syncthreads();
        #pragma unroll 4
        for (int i = 0; i < 128; i++) {
            float dv = sDc[sl*132 + i];
            const float* wr = sw + (ic*128 + i)*36 + jl;
            #pragma unroll
            for (int k = 0; k < 8; k++) y[k] += dv * wr[k*4];
        }
    }
    float pv = 0.f;
    #pragma unroll
    for (int k = 0; k < 8; k++)
        pv += y[k] * g_d[sg*64 + sl][jt*32 + jl + k*4];
    pv += __shfl_down_sync(0xffffffffu, pv, 2);
    pv += __shfl_down_sync(0xffffffffu, pv, 1);
    if (jl == 0) g_kpart[jt*512 + sg*64 + sl] = pv;
}

// ---------------- launch 6: normalize ----------------
__global__ void k_fin(const float* __restrict__ ap, float* __restrict__ out) {
    int n1 = blockIdx.x, n2 = threadIdx.x;
    float s1 = 0.f, s2 = 0.f;
    #pragma unroll
    for (int q = 0; q < 16; q++) {
        s1 += g_kpart[q*512 + n1];
        s2 += g_kpart[q*512 + NSEQ + n2];
    }
    float a0 = ap[0];
    out[n1*NSEQ + n2] = a0*a0 * g_Kraw[n1*NSEQ + n2] * rsqrtf(s1) * rsqrtf(s2);
}

// ---------------- launch ----------------
extern "C" void kernel_launch(void* const* d_in, const int* in_sizes, int n_in,
                              void* d_out, int out_size) {
    const int*   X1 = (const int*)d_in[0];
    const int*   X2 = (const int*)d_in[1];
    const float* W  = (const float*)d_in[2];
    const float* b  = (const float*)d_in[3];
    const float* wp = (const float*)d_in[4];
    const float* a  = (const float*)d_in[5];
    float* out = (float*)d_out;

    float* kraw;  cudaGetSymbolAddress((void**)&kraw, g_Kraw);

    const int SMEM_MMA  = (64*516 + 2*128*68) * 4;      // 201728 B
    const int SMEM_QUAD = (512*36 + 64*132) * 4;        // 107520 B
    cudaFuncSetAttribute(k_mma,  cudaFuncAttributeMaxDynamicSharedMemorySize, SMEM_MMA);
    cudaFuncSetAttribute(k_quad, cudaFuncAttributeMaxDynamicSharedMemorySize, SMEM_QUAD);

    k_init<<<1024 + 512, 256>>>(wp, X1, X2);
    k_Eg<<<dim3(84, 2), 256>>>(W, b);
    k_SG<<<2*NSEQ, 256>>>(X1, X2);
    k_mma<<<dim3(4, 256), 512, SMEM_MMA>>>(X1, kraw);
    k_quad<<<dim3(16, 8), 256, SMEM_QUAD>>>();
    k_fin<<<NSEQ, NSEQ>>>(a, out);
}

// round 7
// speedup vs baseline: 2.3413x; 1.4594x over previous
#include <cuda_runtime.h>
#include <math.h>
#include <cstdint>

#define NSEQ 256
#define LL   512
#define NAA  21
#define DD   128
#define EDIM (NAA*DD)   // 2688

// ---------------- scratch (static device globals; no allocation) ----------------
__device__ __align__(16) float g_w[LL*LL];               // tf32-rounded sigmoid'd 512x512
__device__ __align__(16) float g_E4[4][2*NSEQ][EDIM];    // E partials (4 l-quarters)
__device__ __align__(16) float g_G1[(size_t)NSEQ*LL*NAA];    // G1[n1][l][c]
__device__ __align__(16) float g_G2T[(size_t)LL*NAA*NSEQ];   // G2T[l][c][n2]
__device__ __align__(16) int   g_X1T[LL*NSEQ];
__device__ __align__(16) int   g_X2T[LL*NSEQ];
__device__ __align__(16) float g_d[2*NSEQ][LL];
__device__ __align__(16) float g_kpart[16*2*NSEQ];
__device__ __align__(16) float g_Kraw[NSEQ*NSEQ];

// ---------------- helpers ----------------
__device__ __forceinline__ float to_tf32(float x) {
    float r; asm("cvt.rna.tf32.f32 %0, %1;" : "=f"(r) : "f"(x)); return r;
}
__device__ __forceinline__ void mma_tf32(float* d, const uint32_t* a, uint32_t b0, uint32_t b1) {
    asm volatile(
        "mma.sync.aligned.m16n8k8.row.col.f32.tf32.tf32.f32 "
        "{%0,%1,%2,%3}, {%4,%5,%6,%7}, {%8,%9}, {%0,%1,%2,%3};"
        : "+f"(d[0]), "+f"(d[1]), "+f"(d[2]), "+f"(d[3])
        : "r"(a[0]), "r"(a[1]), "r"(a[2]), "r"(a[3]), "r"(b0), "r"(b1));
}
__device__ __forceinline__ uint32_t smem_u32(const void* p) {
    uint32_t a;
    asm("{ .reg .u64 t; cvta.to.shared.u64 t, %1; cvt.u32.u64 %0, t; }" : "=r"(a) : "l"(p));
    return a;
}
__device__ __forceinline__ void cp16(uint32_t dst, const void* src) {
    asm volatile("cp.async.cg.shared.global [%0], [%1], 16;" :: "r"(dst), "l"(src));
}
#define CP_COMMIT() asm volatile("cp.async.commit_group;" ::: "memory")
#define CP_WAIT0()  asm volatile("cp.async.wait_group 0;" ::: "memory")
#define CP_WAIT1()  asm volatile("cp.async.wait_group 1;" ::: "memory")

// ---------------- launch 1: w = tf32(sigmoid(sym(w_param))) + X transposes ----------------
__global__ void k_init(const float* __restrict__ wp,
                       const int* __restrict__ X1, const int* __restrict__ X2) {
    int bid = blockIdx.x;
    if (bid < 1024) {
        int idx = bid*256 + threadIdx.x;
        int i = idx >> 9, j = idx & (LL-1);
        float v = 0.f;
        if (i > j)      v = wp[i*(i-1)/2 + j];
        else if (j > i) v = wp[j*(j-1)/2 + i];
        g_w[idx] = to_tf32(1.f / (1.f + expf(-v)));
    } else {
        int q = bid - 1024;
        int n = q & 255, set = q >> 8;
        const int* X = set ? (X2 + n*LL) : (X1 + n*LL);
        int* T = set ? g_X2T : g_X1T;
        for (int l = threadIdx.x; l < LL; l += 256) T[l*NSEQ + n] = X[l];
    }
}

// ---------------- launch 2: E gather-sum partials over 4 l-quarters ----------------
__global__ void __launch_bounds__(256) k_Eg(const float* __restrict__ W, const float* __restrict__ b) {
    int col0 = blockIdx.x * 32;
    int sg   = blockIdx.y;
    int lz   = blockIdx.z;             // l-quarter 0..3
    const int* XT = sg ? g_X2T : g_X1T;
    __shared__ float sR[168*35];       // 8 l x 21 rows x 32 cols, stride 35 (3*x injective mod 32)
    __shared__ int   sXc[8*256];
    int t = threadIdx.x;
    float acc[32];
    if (lz == 0) {
        #pragma unroll
        for (int c = 0; c < 32; c++) acc[c] = b[col0 + c];
    } else {
        #pragma unroll
        for (int c = 0; c < 32; c++) acc[c] = 0.f;
    }
    int lbase = lz * 128;
    for (int l0 = lbase; l0 < lbase + 128; l0 += 8) {
        __syncthreads();
        for (int f = t; f < 168*32; f += 256) {
            int row = f >> 5, c = f & 31;
            int l = row / 21, r = row - l*21;
            sR[row*35 + c] = W[(size_t)((l0+l)*NAA + r)*EDIM + col0 + c];
        }
        #pragma unroll
        for (int q = 0; q < 8; q++) sXc[q*256 + t] = XT[(l0+q)*NSEQ + t];
        __syncthreads();
        #pragma unroll
        for (int i = 0; i < 8; i++) {
            const float* base = sR + (i*21 + sXc[i*256 + t])*35;
            #pragma unroll
            for (int c = 0; c < 32; c++) acc[c] += base[c];
        }
    }
    float* Er = g_E4[lz][sg*NSEQ + t] + col0;
    #pragma unroll
    for (int c = 0; c < 8; c++)
        ((float4*)Er)[c] = make_float4(acc[4*c], acc[4*c+1], acc[4*c+2], acc[4*c+3]);
}

// ---------------- launch 3: fused S (warp-per-pair) + gather tables + diag ----------------
__global__ void __launch_bounds__(256) k_SG(const int* __restrict__ X1, const int* __restrict__ X2) {
    int seq = blockIdx.x;
    __shared__ float sE[EDIM];
    __shared__ float sS[NAA*NAA];
    __shared__ int   sX[LL];
    int tid = threadIdx.x, warp = tid >> 5, lane = tid & 31;
    const int* X = (seq < NSEQ) ? (X1 + seq*LL) : (X2 + (seq-NSEQ)*LL);
    for (int i = tid; i < EDIM/4; i += 256) {
        float4 a = ((const float4*)g_E4[0][seq])[i];
        float4 b = ((const float4*)g_E4[1][seq])[i];
        float4 c = ((const float4*)g_E4[2][seq])[i];
        float4 d = ((const float4*)g_E4[3][seq])[i];
        ((float4*)sE)[i] = make_float4(a.x+b.x+c.x+d.x, a.y+b.y+c.y+d.y,
                                       a.z+b.z+c.z+d.z, a.w+b.w+c.w+d.w);
    }
    for (int i = tid; i < LL; i += 256) sX[i] = X[i];
    __syncthreads();
    for (int e = warp; e < NAA*NAA; e += 8) {
        int a = e / NAA, c = e - a*NAA;
        float4 pa = *(const float4*)(sE + a*DD + lane*4);
        float4 pc = *(const float4*)(sE + c*DD + lane*4);
        float s = pa.x*pc.x + pa.y*pc.y + pa.z*pc.z + pa.w*pc.w;
        #pragma unroll
        for (int o = 16; o; o >>= 1) s += __shfl_xor_sync(0xffffffffu, s, o);
        if (lane == 0) sS[e] = s;
    }
    __syncthreads();
    if (seq < NSEQ) {
        float* G = g_G1 + (size_t)seq*LL*NAA;
        for (int idx = tid; idx < LL*NAA; idx += 256) {
            int l = idx / NAA, c = idx - l*NAA;
            G[idx] = sS[sX[l]*NAA + c];
        }
    } else {
        int n2 = seq - NSEQ;
        for (int idx = tid; idx < LL*NAA; idx += 256) {
            int l = idx / NAA, c = idx - l*NAA;
            g_G2T[(size_t)idx*NSEQ + n2] = sS[c*NAA + sX[l]];
        }
    }
    for (int l = tid; l < LL; l += 256)
        g_d[seq][l] = sS[sX[l]*NAA + sX[l]];
}

// ---------------- launch 4: HMMA tf32 GEMM + fold, 16 warps, k-split ----------------
// Block = (n1, 64 n2). 16 warps: kg = warp&1 (k-half of each kc), ph = (warp>>1)&1 (m 32),
// jq = warp>>2 (32 j of 128-j tile, nt=4). LDS/HMMA = 2.0.
__global__ void __launch_bounds__(512, 1)
k_mma(const int* __restrict__ X1, float* __restrict__ kraw) {
    extern __shared__ float sm[];
    float* sS  = sm;                       // [64 pairs][516 k]
    float* sW0 = sm + 64*516;              // [128 j][68 k]
    float* sW1 = sW0 + 128*68;
    float* sG1 = sW0;                      // phase-1 union
    int*   sX1 = (int*)(sW0 + LL*NAA);
    float* sRed = sW0;                     // epilogue union (64 rows x 8)

    int tid  = threadIdx.x;
    int warp = tid >> 5, lane = tid & 31;
    int g = lane >> 2, t2 = lane & 3;
    int kg = warp & 1, ph = (warp >> 1) & 1, jq = warp >> 2;   // jq 0..3
    int n1 = blockIdx.y;
    int n2base = blockIdx.x * 64;

    // ---- phase 1: stage G1[n1] + X1 row, build subs^T (tf32) ----
    const float* G1p = g_G1 + (size_t)n1*LL*NAA;
    for (int i = tid; i < LL*NAA/4; i += 512)
        ((float4*)sG1)[i] = ((const float4*)G1p)[i];
    for (int i = tid; i < LL; i += 512) sX1[i] = X1[n1*LL + i];
    __syncthreads();
    {
        int p = tid & 63;
        int n2 = n2base + p;
        for (int l = tid >> 6; l < LL; l += 8) {
            int x2 = g_X2T[l*NSEQ + n2];
            int c  = sX1[l];
            float v = 0.5f*(sG1[l*NAA + x2] + g_G2T[(size_t)(l*NAA + c)*NSEQ + n2]);
            sS[p*516 + l] = to_tf32(v);
        }
    }
    __syncthreads();

    // ---- phase 2: Y = subs @ w via mma.sync, w staged by cp.async double-buffer ----
    float fr[2][2] = {{0.f,0.f},{0.f,0.f}};
    uint32_t swb[2] = { smem_u32(sW0), smem_u32(sW1) };

    for (int jt = 0; jt < 4; jt++) {
        float acc[2][4][4];
        #pragma unroll
        for (int m = 0; m < 2; m++)
            #pragma unroll
            for (int n = 0; n < 4; n++)
                #pragma unroll
                for (int c = 0; c < 4; c++) acc[m][n][c] = 0.f;

        // prologue: stage kc=0 into buf0 (128 rows x 64 floats, stride 68)
        #pragma unroll
        for (int q = 0; q < 4; q++) {
            int idx = tid + q*512;
            int row = idx >> 4, c16 = idx & 15;
            cp16(swb[0] + (uint32_t)(row*272 + c16*16),
                 g_w + (size_t)(jt*128 + row)*LL + c16*4);
        }
        CP_COMMIT();

        for (int kc = 0; kc < 8; kc++) {
            if (kc < 7) {
                uint32_t dstb = swb[(kc+1) & 1];
                #pragma unroll
                for (int q = 0; q < 4; q++) {
                    int idx = tid + q*512;
                    int row = idx >> 4, c16 = idx & 15;
                    cp16(dstb + (uint32_t)(row*272 + c16*16),
                         g_w + (size_t)(jt*128 + row)*LL + (kc+1)*64 + c16*4);
                }
                CP_COMMIT();
                CP_WAIT1();
            } else {
                CP_WAIT0();
            }
            __syncthreads();
            const float* wb = (kc & 1) ? sW1 : sW0;
            #pragma unroll
            for (int s = 0; s < 4; s++) {
                int ks = kg*4 + s;
                int ko = kc*64 + ks*8;
                uint32_t a[2][4];
                #pragma unroll
                for (int mt = 0; mt < 2; mt++) {
                    const float* ab = sS + (ph*32 + mt*16 + g)*516 + ko + t2;
                    a[mt][0] = __float_as_uint(ab[0]);
                    a[mt][1] = __float_as_uint(ab[8*516]);
                    a[mt][2] = __float_as_uint(ab[4]);
                    a[mt][3] = __float_as_uint(ab[8*516 + 4]);
                }
                #pragma unroll
                for (int nt = 0; nt < 4; nt++) {
                    const float* bb = wb + (jq*32 + nt*8 + g)*68 + ks*8 + t2;
                    uint32_t b0 = __float_as_uint(bb[0]);
                    uint32_t b1 = __float_as_uint(bb[4]);
                    mma_tf32(acc[0][nt], a[0], b0, b1);
                    mma_tf32(acc[1][nt], a[1], b0, b1);
                }
            }
            __syncthreads();   // all warps done reading wb before re-staging
        }
        // fold this jt (partial Y over this warp's k-half; linear -> adds via sRed)
        #pragma unroll
        for (int mt = 0; mt < 2; mt++) {
            const float* s0 = sS + (ph*32 + mt*16 + g)*516;
            const float* s8 = s0 + 8*516;
            #pragma unroll
            for (int nt = 0; nt < 4; nt++) {
                int j = jt*128 + jq*32 + nt*8 + 2*t2;
                fr[mt][0] += acc[mt][nt][0]*s0[j] + acc[mt][nt][1]*s0[j+1];
                fr[mt][1] += acc[mt][nt][2]*s8[j] + acc[mt][nt][3]*s8[j+1];
            }
        }
    }
    __syncthreads();

    #pragma unroll
    for (int mt = 0; mt < 2; mt++)
        #pragma unroll
        for (int h = 0; h < 2; h++) {
            float v = fr[mt][h];
            v += __shfl_down_sync(0xffffffffu, v, 2);
            v += __shfl_down_sync(0xffffffffu, v, 1);
            if (t2 == 0) sRed[(ph*32 + mt*16 + h*8 + g)*8 + kg*4 + jq] = v;
        }
    __syncthreads();
    if (tid < 64) {
        float s = 0.f;
        #pragma unroll
        for (int q = 0; q < 8; q++) s += sRed[tid*8 + q];
        kraw[n1*NSEQ + n2base + tid] = s;
    }
}

// ---------------- launch 5: kpart[jt][s] partial d^T w d ----------------
__global__ void __launch_bounds__(256) k_quad() {
    extern __shared__ float qm[];
    float* sw  = qm;                 // [512 i][36]
    float* sDc = qm + 512*36;        // [64 s][132]
    int jt = blockIdx.x, sg = blockIdx.y;
    int t = threadIdx.x, sl = t >> 2, jl = t & 3;

    for (int f = t; f < 512*8; f += 256) {
        int i = f >> 3, c4 = f & 7;
        float4 v = *(const float4*)(g_w + (size_t)i*LL + jt*32 + c4*4);
        *(float4*)(sw + i*36 + c4*4) = v;
    }
    float y[8];
    #pragma unroll
    for (int k = 0; k < 8; k++) y[k] = 0.f;
    for (int ic = 0; ic < 4; ic++) {
        __syncthreads();
        for (int f = t; f < 64*32; f += 256) {
            int s = f >> 5, c4 = f & 31;
            float4 v = *(const float4*)(&g_d[sg*64 + s][ic*128 + c4*4]);
            *(float4*)(sDc + s*132 + c4*4) = v;
        }
        __syncthreads();
        #pragma unroll 4
        for (int i = 0; i < 128; i++) {
            float dv = sDc[sl*132 + i];
            const float* wr = sw + (ic*128 + i)*36 + jl;
            #pragma unroll
            for (int k = 0; k < 8; k++) y[k] += dv * wr[k*4];
        }
    }
    float pv = 0.f;
    #pragma unroll
    for (int k = 0; k < 8; k++)
        pv += y[k] * g_d[sg*64 + sl][jt*32 + jl + k*4];
    pv += __shfl_down_sync(0xffffffffu, pv, 2);
    pv += __shfl_down_sync(0xffffffffu, pv, 1);
    if (jl == 0) g_kpart[jt*512 + sg*64 + sl] = pv;
}

// ---------------- launch 6: normalize ----------------
__global__ void k_fin(const float* __restrict__ ap, float* __restrict__ out) {
    int n1 = blockIdx.x, n2 = threadIdx.x;
    float s1 = 0.f, s2 = 0.f;
    #pragma unroll
    for (int q = 0; q < 16; q++) {
        s1 += g_kpart[q*512 + n1];
        s2 += g_kpart[q*512 + NSEQ + n2];
    }
    float a0 = ap[0];
    out[n1*NSEQ + n2] = a0*a0 * g_Kraw[n1*NSEQ + n2] * rsqrtf(s1) * rsqrtf(s2);
}

// ---------------- launch ----------------
extern "C" void kernel_launch(void* const* d_in, const int* in_sizes, int n_in,
                              void* d_out, int out_size) {
    const int*   X1 = (const int*)d_in[0];
    const int*   X2 = (const int*)d_in[1];
    const float* W  = (const float*)d_in[2];
    const float* b  = (const float*)d_in[3];
    const float* wp = (const float*)d_in[4];
    const float* a  = (const float*)d_in[5];
    float* out = (float*)d_out;

    float* kraw;  cudaGetSymbolAddress((void**)&kraw, g_Kraw);

    const int SMEM_MMA  = (64*516 + 2*128*68) * 4;      // 201728 B
    const int SMEM_QUAD = (512*36 + 64*132) * 4;        // 107520 B
    cudaFuncSetAttribute(k_mma,  cudaFuncAttributeMaxDynamicSharedMemorySize, SMEM_MMA);
    cudaFuncSetAttribute(k_quad, cudaFuncAttributeMaxDynamicSharedMemorySize, SMEM_QUAD);

    k_init<<<1024 + 512, 256>>>(wp, X1, X2);
    k_Eg<<<dim3(84, 2, 4), 256>>>(W, b);
    k_SG<<<2*NSEQ, 256>>>(X1, X2);
    k_mma<<<dim3(4, 256), 512, SMEM_MMA>>>(X1, kraw);
    k_quad<<<dim3(16, 8), 256, SMEM_QUAD>>>();
    k_fin<<<NSEQ, NSEQ>>>(a, out);
}

// round 8
// speedup vs baseline: 2.9245x; 1.2491x over previous
#include <cuda_runtime.h>
#include <cuda_fp16.h>
#include <math.h>
#include <cstdint>

#define NSEQ 256
#define LL   512
#define NAA  21
#define DD   128
#define EDIM (NAA*DD)   // 2688

// ---------------- scratch (static device globals; no allocation) ----------------
__device__ __align__(16) float  g_w[LL*LL];              // fp32 sigmoid'd w (k_quad)
__device__ __align__(16) __half g_wh[LL*LL];             // fp16 w for MMA
__device__ __align__(16) float  g_E4[4][2*NSEQ][EDIM];   // E partials (4 l-quarters)
__device__ __align__(16) __half g_G1h[(size_t)NSEQ*LL*NAA];   // G1[n1][l][c] fp16
__device__ __align__(16) __half g_G2Th[(size_t)LL*NAA*NSEQ];  // G2T[l][c][n2] fp16
__device__ __align__(16) int    g_X1T[LL*NSEQ];
__device__ __align__(16) int    g_X2T[LL*NSEQ];
__device__ __align__(16) float  g_d[2*NSEQ][LL];
__device__ __align__(16) float  g_kpart[16*2*NSEQ];
__device__ __align__(16) float  g_Kraw[NSEQ*NSEQ];

// ---------------- helpers ----------------
__device__ __forceinline__ void mma_f16(float* d, const uint32_t* a, uint32_t b0, uint32_t b1) {
    asm volatile(
        "mma.sync.aligned.m16n8k16.row.col.f32.f16.f16.f32 "
        "{%0,%1,%2,%3}, {%4,%5,%6,%7}, {%8,%9}, {%0,%1,%2,%3};"
        : "+f"(d[0]), "+f"(d[1]), "+f"(d[2]), "+f"(d[3])
        : "r"(a[0]), "r"(a[1]), "r"(a[2]), "r"(a[3]), "r"(b0), "r"(b1));
}
__device__ __forceinline__ uint32_t smem_u32(const void* p) {
    uint32_t a;
    asm("{ .reg .u64 t; cvta.to.shared.u64 t, %1; cvt.u32.u64 %0, t; }" : "=r"(a) : "l"(p));
    return a;
}
__device__ __forceinline__ void cp16(uint32_t dst, const void* src) {
    asm volatile("cp.async.cg.shared.global [%0], [%1], 16;" :: "r"(dst), "l"(src));
}
#define CP_COMMIT() asm volatile("cp.async.commit_group;" ::: "memory")
#define CP_WAIT0()  asm volatile("cp.async.wait_group 0;" ::: "memory")
#define CP_WAIT1()  asm volatile("cp.async.wait_group 1;" ::: "memory")
__device__ __forceinline__ float h_lo(uint32_t w) { return __half2float(__ushort_as_half((unsigned short)(w & 0xffff))); }
__device__ __forceinline__ float h_hi(uint32_t w) { return __half2float(__ushort_as_half((unsigned short)(w >> 16))); }

// ---------------- launch 1: w (fp32 + fp16) + X transposes ----------------
__global__ void k_init(const float* __restrict__ wp,
                       const int* __restrict__ X1, const int* __restrict__ X2) {
    int bid = blockIdx.x;
    if (bid < 1024) {
        int idx = bid*256 + threadIdx.x;
        int i = idx >> 9, j = idx & (LL-1);
        float v = 0.f;
        if (i > j)      v = wp[i*(i-1)/2 + j];
        else if (j > i) v = wp[j*(j-1)/2 + i];
        float s = 1.f / (1.f + expf(-v));
        g_w[idx]  = s;
        g_wh[idx] = __float2half_rn(s);
    } else {
        int q = bid - 1024;
        int n = q & 255, set = q >> 8;
        const int* X = set ? (X2 + n*LL) : (X1 + n*LL);
        int* T = set ? g_X2T : g_X1T;
        for (int l = threadIdx.x; l < LL; l += 256) T[l*NSEQ + n] = X[l];
    }
}

// ---------------- launch 2: E gather-sum partials over 4 l-quarters ----------------
__global__ void __launch_bounds__(256) k_Eg(const float* __restrict__ W, const float* __restrict__ b) {
    int col0 = blockIdx.x * 32;
    int sg   = blockIdx.y;
    int lz   = blockIdx.z;
    const int* XT = sg ? g_X2T : g_X1T;
    __shared__ float sR[168*35];       // 8 l x 21 rows x 32 cols, stride 35 (3*x injective mod 32)
    __shared__ int   sXc[8*256];
    int t = threadIdx.x;
    float acc[32];
    if (lz == 0) {
        #pragma unroll
        for (int c = 0; c < 32; c++) acc[c] = b[col0 + c];
    } else {
        #pragma unroll
        for (int c = 0; c < 32; c++) acc[c] = 0.f;
    }
    int lbase = lz * 128;
    for (int l0 = lbase; l0 < lbase + 128; l0 += 8) {
        __syncthreads();
        for (int f = t; f < 168*32; f += 256) {
            int row = f >> 5, c = f & 31;
            int l = row / 21, r = row - l*21;
            sR[row*35 + c] = W[(size_t)((l0+l)*NAA + r)*EDIM + col0 + c];
        }
        #pragma unroll
        for (int q = 0; q < 8; q++) sXc[q*256 + t] = XT[(l0+q)*NSEQ + t];
        __syncthreads();
        #pragma unroll
        for (int i = 0; i < 8; i++) {
            const float* base = sR + (i*21 + sXc[i*256 + t])*35;
            #pragma unroll
            for (int c = 0; c < 32; c++) acc[c] += base[c];
        }
    }
    float* Er = g_E4[lz][sg*NSEQ + t] + col0;
    #pragma unroll
    for (int c = 0; c < 8; c++)
        ((float4*)Er)[c] = make_float4(acc[4*c], acc[4*c+1], acc[4*c+2], acc[4*c+3]);
}

// ---------------- launch 3: fused S + gather tables (fp16) + diag ----------------
__global__ void __launch_bounds__(256) k_SG(const int* __restrict__ X1, const int* __restrict__ X2) {
    int seq = blockIdx.x;
    __shared__ float sE[EDIM];
    __shared__ float sS[NAA*NAA];
    __shared__ int   sX[LL];
    int tid = threadIdx.x, warp = tid >> 5, lane = tid & 31;
    const int* X = (seq < NSEQ) ? (X1 + seq*LL) : (X2 + (seq-NSEQ)*LL);
    for (int i = tid; i < EDIM/4; i += 256) {
        float4 a = ((const float4*)g_E4[0][seq])[i];
        float4 b = ((const float4*)g_E4[1][seq])[i];
        float4 c = ((const float4*)g_E4[2][seq])[i];
        float4 d = ((const float4*)g_E4[3][seq])[i];
        ((float4*)sE)[i] = make_float4(a.x+b.x+c.x+d.x, a.y+b.y+c.y+d.y,
                                       a.z+b.z+c.z+d.z, a.w+b.w+c.w+d.w);
    }
    for (int i = tid; i < LL; i += 256) sX[i] = X[i];
    __syncthreads();
    for (int e = warp; e < NAA*NAA; e += 8) {
        int a = e / NAA, c = e - a*NAA;
        float4 pa = *(const float4*)(sE + a*DD + lane*4);
        float4 pc = *(const float4*)(sE + c*DD + lane*4);
        float s = pa.x*pc.x + pa.y*pc.y + pa.z*pc.z + pa.w*pc.w;
        #pragma unroll
        for (int o = 16; o; o >>= 1) s += __shfl_xor_sync(0xffffffffu, s, o);
        if (lane == 0) sS[e] = s;
    }
    __syncthreads();
    if (seq < NSEQ) {
        __half* G = g_G1h + (size_t)seq*LL*NAA;
        for (int idx = tid; idx < LL*NAA; idx += 256) {
            int l = idx / NAA, c = idx - l*NAA;
            G[idx] = __float2half_rn(sS[sX[l]*NAA + c]);
        }
    } else {
        int n2 = seq - NSEQ;
        for (int idx = tid; idx < LL*NAA; idx += 256) {
            int l = idx / NAA, c = idx - l*NAA;
            g_G2Th[(size_t)idx*NSEQ + n2] = __float2half_rn(sS[c*NAA + sX[l]]);
        }
    }
    for (int l = tid; l < LL; l += 256)
        g_d[seq][l] = sS[sX[l]*NAA + sX[l]];
}

// ---------------- launch 4: fp16 HMMA k16 GEMM + fold, 2 blocks/SM ----------------
// Block = (n1, 64 n2). 8 warps: ph = warp&1 (m-half 32), jq = warp>>1 (32 j of 128-j tile).
__global__ void __launch_bounds__(256, 2)
k_mma(const int* __restrict__ X1, float* __restrict__ kraw) {
    extern __shared__ char smraw[];
    __half* sS = (__half*)smraw;                 // 64*520*2 = 66560 B
    char* uni = smraw + 66560;
    __half* sW0 = (__half*)uni;                  // 128*72*2 = 18432 B
    __half* sW1 = (__half*)(uni + 18432);
    __half* sG1 = (__half*)uni;                  // phase-1 union (21504 B)
    int*   sX1  = (int*)(uni + 21504);           // 2048 B
    float* sRed = (float*)uni;                   // epilogue union (64*4 f)

    const uint32_t* sS32 = (const uint32_t*)sS;
    const uint32_t* sW32[2] = { (const uint32_t*)sW0, (const uint32_t*)sW1 };

    int tid  = threadIdx.x;
    int warp = tid >> 5, lane = tid & 31;
    int g = lane >> 2, t2 = lane & 3;
    int ph = warp & 1, jq = warp >> 1;
    int n1 = blockIdx.y;
    int n2base = blockIdx.x * 64;

    // ---- phase 1: stage G1[n1] (fp16) + X1 row, build subs^T in fp16 ----
    const uint4* G1p = (const uint4*)(g_G1h + (size_t)n1*LL*NAA);
    for (int f = tid; f < LL*NAA*2/16; f += 256) ((uint4*)sG1)[f] = G1p[f];
    for (int i = tid; i < LL; i += 256) sX1[i] = X1[n1*LL + i];
    __syncthreads();
    {
        int p = tid & 63;
        int n2 = n2base + p;
        for (int l = tid >> 6; l < LL; l += 4) {
            int x2 = g_X2T[l*NSEQ + n2];
            float g1 = __half2float(sG1[l*NAA + x2]);
            float g2 = __half2float(g_G2Th[(size_t)(l*NAA + sX1[l])*NSEQ + n2]);
            sS[p*520 + l] = __float2half_rn(0.5f*(g1 + g2));
        }
    }
    __syncthreads();

    // ---- phase 2: Y = subs @ w (fp16 k16 MMA), w cp.async double-buffered ----
    float fr[2][2] = {{0.f,0.f},{0.f,0.f}};
    uint32_t swb[2] = { smem_u32(sW0), smem_u32(sW1) };

    for (int jt = 0; jt < 4; jt++) {
        float acc[2][4][4];
        #pragma unroll
        for (int m = 0; m < 2; m++)
            #pragma unroll
            for (int n = 0; n < 4; n++)
                #pragma unroll
                for (int c = 0; c < 4; c++) acc[m][n][c] = 0.f;

        // prologue: stage kc=0 into buf0 (128 rows x 64 fp16, row stride 72 fp16 = 144 B)
        #pragma unroll
        for (int q = 0; q < 4; q++) {
            int idx = tid + q*256;
            int row = idx >> 3, c8 = idx & 7;
            cp16(swb[0] + (uint32_t)(row*144 + c8*16),
                 g_wh + (size_t)(jt*128 + row)*LL + c8*8);
        }
        CP_COMMIT();

        for (int kc = 0; kc < 8; kc++) {
            if (kc < 7) {
                uint32_t dstb = swb[(kc+1) & 1];
                #pragma unroll
                for (int q = 0; q < 4; q++) {
                    int idx = tid + q*256;
                    int row = idx >> 3, c8 = idx & 7;
                    cp16(dstb + (uint32_t)(row*144 + c8*16),
                         g_wh + (size_t)(jt*128 + row)*LL + (kc+1)*64 + c8*8);
                }
                CP_COMMIT();
                CP_WAIT1();
            } else {
                CP_WAIT0();
            }
            __syncthreads();
            const uint32_t* wb = sW32[kc & 1];
            #pragma unroll
            for (int ks = 0; ks < 4; ks++) {
                int kw = kc*32 + ks*8;          // word offset (fp16x2 units)
                uint32_t a[2][4];
                #pragma unroll
                for (int mt = 0; mt < 2; mt++) {
                    int r0 = (ph*32 + mt*16 + g)*260;
                    a[mt][0] = sS32[r0 + kw + t2];
                    a[mt][1] = sS32[r0 + 8*260 + kw + t2];
                    a[mt][2] = sS32[r0 + kw + t2 + 4];
                    a[mt][3] = sS32[r0 + 8*260 + kw + t2 + 4];
                }
                #pragma unroll
                for (int nt = 0; nt < 4; nt++) {
                    int jw = (jq*32 + nt*8 + g)*36 + ks*8 + t2;
                    uint32_t b0 = wb[jw];
                    uint32_t b1 = wb[jw + 4];
                    mma_f16(acc[0][nt], a[0], b0, b1);
                    mma_f16(acc[1][nt], a[1], b0, b1);
                }
            }
            __syncthreads();
        }
        // fold this jt: fr += Y[p,j] * subs[p,j]
        #pragma unroll
        for (int mt = 0; mt < 2; mt++) {
            int r0 = (ph*32 + mt*16 + g)*260;
            #pragma unroll
            for (int nt = 0; nt < 4; nt++) {
                int jw = (jt*128 + jq*32 + nt*8) / 2 + t2;
                uint32_t w0 = sS32[r0 + jw];
                uint32_t w8 = sS32[r0 + 8*260 + jw];
                fr[mt][0] += acc[mt][nt][0]*h_lo(w0) + acc[mt][nt][1]*h_hi(w0);
                fr[mt][1] += acc[mt][nt][2]*h_lo(w8) + acc[mt][nt][3]*h_hi(w8);
            }
        }
    }
    __syncthreads();

    #pragma unroll
    for (int mt = 0; mt < 2; mt++)
        #pragma unroll
        for (int h = 0; h < 2; h++) {
            float v = fr[mt][h];
            v += __shfl_down_sync(0xffffffffu, v, 2);
            v += __shfl_down_sync(0xffffffffu, v, 1);
            if (t2 == 0) sRed[(ph*32 + mt*16 + h*8 + g)*4 + jq] = v;
        }
    __syncthreads();
    if (tid < 64)
        kraw[n1*NSEQ + n2base + tid] =
            sRed[tid*4+0] + sRed[tid*4+1] + sRed[tid*4+2] + sRed[tid*4+3];
}

// ---------------- launch 5: kpart[jt][s] partial d^T w d (fp32) ----------------
__global__ void __launch_bounds__(256) k_quad() {
    extern __shared__ float qm[];
    float* sw  = qm;                 // [512 i][36]
    float* sDc = qm + 512*36;        // [64 s][132]
    int jt = blockIdx.x, sg = blockIdx.y;
    int t = threadIdx.x, sl = t >> 2, jl = t & 3;

    for (int f = t; f < 512*8; f += 256) {
        int i = f >> 3, c4 = f & 7;
        float4 v = *(const float4*)(g_w + (size_t)i*LL + jt*32 + c4*4);
        *(float4*)(sw + i*36 + c4*4) = v;
    }
    float y[8];
    #pragma unroll
    for (int k = 0; k < 8; k++) y[k] = 0.f;
    for (int ic = 0; ic < 4; ic++) {
        __syncthreads();
        for (int f = t; f < 64*32; f += 256) {
            int s = f >> 5, c4 = f & 31;
            float4 v = *(const float4*)(&g_d[sg*64 + s][ic*128 + c4*4]);
            *(float4*)(sDc + s*132 + c4*4) = v;
        }
        __syncthreads();
        #pragma unroll 4
        for (int i = 0; i < 128; i++) {
            float dv = sDc[sl*132 + i];
            const float* wr = sw + (ic*128 + i)*36 + jl;
            #pragma unroll
            for (int k = 0; k < 8; k++) y[k] += dv * wr[k*4];
        }
    }
    float pv = 0.f;
    #pragma unroll
    for (int k = 0; k < 8; k++)
        pv += y[k] * g_d[sg*64 + sl][jt*32 + jl + k*4];
    pv += __shfl_down_sync(0xffffffffu, pv, 2);
    pv += __shfl_down_sync(0xffffffffu, pv, 1);
    if (jl == 0) g_kpart[jt*512 + sg*64 + sl] = pv;
}

// ---------------- launch 6: normalize ----------------
__global__ void k_fin(const float* __restrict__ ap, float* __restrict__ out) {
    int n1 = blockIdx.x, n2 = threadIdx.x;
    float s1 = 0.f, s2 = 0.f;
    #pragma unroll
    for (int q = 0; q < 16; q++) {
        s1 += g_kpart[q*512 + n1];
        s2 += g_kpart[q*512 + NSEQ + n2];
    }
    float a0 = ap[0];
    out[n1*NSEQ + n2] = a0*a0 * g_Kraw[n1*NSEQ + n2] * rsqrtf(s1) * rsqrtf(s2);
}

// ---------------- launch ----------------
extern "C" void kernel_launch(void* const* d_in, const int* in_sizes, int n_in,
                              void* d_out, int out_size) {
    const int*   X1 = (const int*)d_in[0];
    const int*   X2 = (const int*)d_in[1];
    const float* W  = (const float*)d_in[2];
    const float* b  = (const float*)d_in[3];
    const float* wp = (const float*)d_in[4];
    const float* a  = (const float*)d_in[5];
    float* out = (float*)d_out;

    float* kraw;  cudaGetSymbolAddress((void**)&kraw, g_Kraw);

    const int SMEM_MMA  = 66560 + 2*18432;              // 103424 B -> 2 blocks/SM
    const int SMEM_QUAD = (512*36 + 64*132) * 4;        // 107520 B
    cudaFuncSetAttribute(k_mma,  cudaFuncAttributeMaxDynamicSharedMemorySize, SMEM_MMA);
    cudaFuncSetAttribute(k_quad, cudaFuncAttributeMaxDynamicSharedMemorySize, SMEM_QUAD);

    k_init<<<1024 + 512, 256>>>(wp, X1, X2);
    k_Eg<<<dim3(84, 2, 4), 256>>>(W, b);
    k_SG<<<2*NSEQ, 256>>>(X1, X2);
    k_mma<<<dim3(4, 256), 256, SMEM_MMA>>>(X1, kraw);
    k_quad<<<dim3(16, 8), 256, SMEM_QUAD>>>();
    k_fin<<<NSEQ, NSEQ>>>(a, out);
}

// round 9
// speedup vs baseline: 3.0978x; 1.0593x over previous
#include <cuda_runtime.h>
#include <cuda_fp16.h>
#include <math.h>
#include <cstdint>

#define NSEQ 256
#define LL   512
#define NAA  21
#define DD   128
#define EDIM (NAA*DD)   // 2688

// ---------------- scratch (static device globals; no allocation) ----------------
__device__ __align__(16) float  g_w[LL*LL];              // fp32 sigmoid'd w (k_quad)
__device__ __align__(16) __half g_wh[LL*LL];             // fp16 w for MMA
__device__ __align__(16) float  g_E4[4][2*NSEQ][EDIM];   // E partials (4 l-quarters)
__device__ __align__(16) __half g_G1h[(size_t)NSEQ*LL*NAA];   // G1[n1][l][c] fp16
__device__ __align__(16) __half g_G2Th[(size_t)LL*NAA*NSEQ];  // G2T[l][c][n2] fp16
__device__ __align__(16) int    g_X1T[LL*NSEQ];
__device__ __align__(16) int    g_X2T[LL*NSEQ];
__device__ __align__(16) float  g_d[2*NSEQ][LL];
__device__ __align__(16) float  g_kpart[16*2*NSEQ];
__device__ __align__(16) float  g_Kraw[NSEQ*NSEQ];

// ---------------- helpers ----------------
__device__ __forceinline__ void mma_f16(float* d, const uint32_t* a, uint32_t b0, uint32_t b1) {
    asm volatile(
        "mma.sync.aligned.m16n8k16.row.col.f32.f16.f16.f32 "
        "{%0,%1,%2,%3}, {%4,%5,%6,%7}, {%8,%9}, {%0,%1,%2,%3};"
        : "+f"(d[0]), "+f"(d[1]), "+f"(d[2]), "+f"(d[3])
        : "r"(a[0]), "r"(a[1]), "r"(a[2]), "r"(a[3]), "r"(b0), "r"(b1));
}
__device__ __forceinline__ void ldsm_x4(uint32_t& r0, uint32_t& r1, uint32_t& r2, uint32_t& r3,
                                        uint32_t addr) {
    asm volatile("ldmatrix.sync.aligned.m8n8.x4.shared.b16 {%0,%1,%2,%3}, [%4];"
                 : "=r"(r0), "=r"(r1), "=r"(r2), "=r"(r3) : "r"(addr));
}
__device__ __forceinline__ uint32_t smem_u32(const void* p) {
    uint32_t a;
    asm("{ .reg .u64 t; cvta.to.shared.u64 t, %1; cvt.u32.u64 %0, t; }" : "=r"(a) : "l"(p));
    return a;
}
__device__ __forceinline__ void cp16(uint32_t dst, const void* src) {
    asm volatile("cp.async.cg.shared.global [%0], [%1], 16;" :: "r"(dst), "l"(src));
}
#define CP_COMMIT() asm volatile("cp.async.commit_group;" ::: "memory")
#define CP_WAIT0()  asm volatile("cp.async.wait_group 0;" ::: "memory")
#define CP_WAIT1()  asm volatile("cp.async.wait_group 1;" ::: "memory")
__device__ __forceinline__ float h_lo(uint32_t w) { return __half2float(__ushort_as_half((unsigned short)(w & 0xffff))); }
__device__ __forceinline__ float h_hi(uint32_t w) { return __half2float(__ushort_as_half((unsigned short)(w >> 16))); }

// ---------------- launch 1: w (fp32 + fp16) + X transposes ----------------
__global__ void k_init(const float* __restrict__ wp,
                       const int* __restrict__ X1, const int* __restrict__ X2) {
    int bid = blockIdx.x;
    if (bid < 1024) {
        int idx = bid*256 + threadIdx.x;
        int i = idx >> 9, j = idx & (LL-1);
        float v = 0.f;
        if (i > j)      v = wp[i*(i-1)/2 + j];
        else if (j > i) v = wp[j*(j-1)/2 + i];
        float s = 1.f / (1.f + expf(-v));
        g_w[idx]  = s;
        g_wh[idx] = __float2half_rn(s);
    } else {
        int q = bid - 1024;
        int n = q & 255, set = q >> 8;
        const int* X = set ? (X2 + n*LL) : (X1 + n*LL);
        int* T = set ? g_X2T : g_X1T;
        for (int l = threadIdx.x; l < LL; l += 256) T[l*NSEQ + n] = X[l];
    }
}

// ---------------- launch 2: E gather-sum partials over 4 l-quarters ----------------
__global__ void __launch_bounds__(256) k_Eg(const float* __restrict__ W, const float* __restrict__ b) {
    int col0 = blockIdx.x * 32;
    int sg   = blockIdx.y;
    int lz   = blockIdx.z;
    const int* XT = sg ? g_X2T : g_X1T;
    __shared__ float sR[168*35];       // 8 l x 21 rows x 32 cols, stride 35 (3*x injective mod 32)
    __shared__ int   sXc[8*256];
    int t = threadIdx.x;
    float acc[32];
    if (lz == 0) {
        #pragma unroll
        for (int c = 0; c < 32; c++) acc[c] = b[col0 + c];
    } else {
        #pragma unroll
        for (int c = 0; c < 32; c++) acc[c] = 0.f;
    }
    int lbase = lz * 128;
    for (int l0 = lbase; l0 < lbase + 128; l0 += 8) {
        __syncthreads();
        for (int f = t; f < 168*32; f += 256) {
            int row = f >> 5, c = f & 31;
            int l = row / 21, r = row - l*21;
            sR[row*35 + c] = W[(size_t)((l0+l)*NAA + r)*EDIM + col0 + c];
        }
        #pragma unroll
        for (int q = 0; q < 8; q++) sXc[q*256 + t] = XT[(l0+q)*NSEQ + t];
        __syncthreads();
        #pragma unroll
        for (int i = 0; i < 8; i++) {
            const float* base = sR + (i*21 + sXc[i*256 + t])*35;
            #pragma unroll
            for (int c = 0; c < 32; c++) acc[c] += base[c];
        }
    }
    float* Er = g_E4[lz][sg*NSEQ + t] + col0;
    #pragma unroll
    for (int c = 0; c < 8; c++)
        ((float4*)Er)[c] = make_float4(acc[4*c], acc[4*c+1], acc[4*c+2], acc[4*c+3]);
}

// ---------------- launch 3: fused S + gather tables (fp16) + diag ----------------
__global__ void __launch_bounds__(256) k_SG(const int* __restrict__ X1, const int* __restrict__ X2) {
    int seq = blockIdx.x;
    __shared__ float sE[EDIM];
    __shared__ float sS[NAA*NAA];
    __shared__ int   sX[LL];
    int tid = threadIdx.x, warp = tid >> 5, lane = tid & 31;
    const int* X = (seq < NSEQ) ? (X1 + seq*LL) : (X2 + (seq-NSEQ)*LL);
    for (int i = tid; i < EDIM/4; i += 256) {
        float4 a = ((const float4*)g_E4[0][seq])[i];
        float4 b = ((const float4*)g_E4[1][seq])[i];
        float4 c = ((const float4*)g_E4[2][seq])[i];
        float4 d = ((const float4*)g_E4[3][seq])[i];
        ((float4*)sE)[i] = make_float4(a.x+b.x+c.x+d.x, a.y+b.y+c.y+d.y,
                                       a.z+b.z+c.z+d.z, a.w+b.w+c.w+d.w);
    }
    for (int i = tid; i < LL; i += 256) sX[i] = X[i];
    __syncthreads();
    for (int e = warp; e < NAA*NAA; e += 8) {
        int a = e / NAA, c = e - a*NAA;
        float4 pa = *(const float4*)(sE + a*DD + lane*4);
        float4 pc = *(const float4*)(sE + c*DD + lane*4);
        float s = pa.x*pc.x + pa.y*pc.y + pa.z*pc.z + pa.w*pc.w;
        #pragma unroll
        for (int o = 16; o; o >>= 1) s += __shfl_xor_sync(0xffffffffu, s, o);
        if (lane == 0) sS[e] = s;
    }
    __syncthreads();
    if (seq < NSEQ) {
        __half* G = g_G1h + (size_t)seq*LL*NAA;
        for (int idx = tid; idx < LL*NAA; idx += 256) {
            int l = idx / NAA, c = idx - l*NAA;
            G[idx] = __float2half_rn(sS[sX[l]*NAA + c]);
        }
    } else {
        int n2 = seq - NSEQ;
        for (int idx = tid; idx < LL*NAA; idx += 256) {
            int l = idx / NAA, c = idx - l*NAA;
            g_G2Th[(size_t)idx*NSEQ + n2] = __float2half_rn(sS[c*NAA + sX[l]]);
        }
    }
    for (int l = tid; l < LL; l += 256)
        g_d[seq][l] = sS[sX[l]*NAA + sX[l]];
}

// ---------------- launch 4: fp16 HMMA k16 GEMM (ldmatrix operands) + fold ----------------
// Block = (n1, 64 n2). 8 warps: ph = warp&1 (m-half 32), jq = warp>>1 (32 j of 128-j tile).
__global__ void __launch_bounds__(256, 2)
k_mma(const int* __restrict__ X1, float* __restrict__ kraw) {
    extern __shared__ char smraw[];
    __half* sS = (__half*)smraw;                 // 64*520*2 = 66560 B
    char* uni = smraw + 66560;
    __half* sW0 = (__half*)uni;                  // 128*72*2 = 18432 B
    __half* sW1 = (__half*)(uni + 18432);
    __half* sG1 = (__half*)uni;                  // phase-1 union (21504 B)
    int*   sX1  = (int*)(uni + 21504);           // 2048 B
    float* sRed = (float*)uni;                   // epilogue union (64*4 f)

    const uint32_t* sS32 = (const uint32_t*)sS;

    int tid  = threadIdx.x;
    int warp = tid >> 5, lane = tid & 31;
    int g = lane >> 2, t2 = lane & 3;
    int ph = warp & 1, jq = warp >> 1;
    int n1 = blockIdx.y;
    int n2base = blockIdx.x * 64;

    // ---- phase 1: stage G1[n1] (fp16) + X1 row, build subs^T in fp16 ----
    const uint4* G1p = (const uint4*)(g_G1h + (size_t)n1*LL*NAA);
    for (int f = tid; f < LL*NAA*2/16; f += 256) ((uint4*)sG1)[f] = G1p[f];
    for (int i = tid; i < LL; i += 256) sX1[i] = X1[n1*LL + i];
    __syncthreads();
    {
        int p = tid & 63;
        int n2 = n2base + p;
        for (int l = tid >> 6; l < LL; l += 4) {
            int x2 = g_X2T[l*NSEQ + n2];
            float g1 = __half2float(sG1[l*NAA + x2]);
            float g2 = __half2float(g_G2Th[(size_t)(l*NAA + sX1[l])*NSEQ + n2]);
            sS[p*520 + l] = __float2half_rn(0.5f*(g1 + g2));
        }
    }
    __syncthreads();

    // ---- ldmatrix lane addressing ----
    uint32_t sSaddr = smem_u32(sS);
    uint32_t swb[2] = { smem_u32(sW0), smem_u32(sW1) };
    // A: lanes 0-15 -> rows m+0..15 at k+0; lanes 16-31 -> rows m+0..15 at k+8
    int laneRowA = lane & 15;
    int laneKA   = (lane >> 4) * 8;
    uint32_t aAddr[2];
    #pragma unroll
    for (int mt = 0; mt < 2; mt++)
        aAddr[mt] = sSaddr + (uint32_t)(((ph*32 + mt*16 + laneRowA)*520 + laneKA)*2);
    // B: matrices (n0-7,k0-7),(n0-7,k8-15),(n8-15,k0-7),(n8-15,k8-15)
    int laneRowB = (lane & 7) + (lane >> 4) * 8;
    int laneKB   = ((lane >> 3) & 1) * 8;
    uint32_t bOff[2];
    #pragma unroll
    for (int ntp = 0; ntp < 2; ntp++)
        bOff[ntp] = (uint32_t)(((jq*32 + ntp*16 + laneRowB)*72 + laneKB)*2);

    // ---- phase 2: Y = subs @ w (fp16 k16 MMA), w cp.async double-buffered ----
    float fr[2][2] = {{0.f,0.f},{0.f,0.f}};

    for (int jt = 0; jt < 4; jt++) {
        float acc[2][4][4];
        #pragma unroll
        for (int m = 0; m < 2; m++)
            #pragma unroll
            for (int n = 0; n < 4; n++)
                #pragma unroll
                for (int c = 0; c < 4; c++) acc[m][n][c] = 0.f;

        // prologue: stage kc=0 into buf0 (128 rows x 64 fp16, row stride 72 fp16 = 144 B)
        #pragma unroll
        for (int q = 0; q < 4; q++) {
            int idx = tid + q*256;
            int row = idx >> 3, c8 = idx & 7;
            cp16(swb[0] + (uint32_t)(row*144 + c8*16),
                 g_wh + (size_t)(jt*128 + row)*LL + c8*8);
        }
        CP_COMMIT();

        for (int kc = 0; kc < 8; kc++) {
            if (kc < 7) {
                uint32_t dstb = swb[(kc+1) & 1];
                #pragma unroll
                for (int q = 0; q < 4; q++) {
                    int idx = tid + q*256;
                    int row = idx >> 3, c8 = idx & 7;
                    cp16(dstb + (uint32_t)(row*144 + c8*16),
                         g_wh + (size_t)(jt*128 + row)*LL + (kc+1)*64 + c8*8);
                }
                CP_COMMIT();
                CP_WAIT1();
            } else {
                CP_WAIT0();
            }
            __syncthreads();
            uint32_t wbuf = swb[kc & 1];
            #pragma unroll
            for (int ks = 0; ks < 4; ks++) {
                uint32_t kbyteA = (uint32_t)((kc*64 + ks*16)*2);
                uint32_t a[2][4], bm[2][4];
                ldsm_x4(a[0][0], a[0][1], a[0][2], a[0][3], aAddr[0] + kbyteA);
                ldsm_x4(a[1][0], a[1][1], a[1][2], a[1][3], aAddr[1] + kbyteA);
                ldsm_x4(bm[0][0], bm[0][1], bm[0][2], bm[0][3], wbuf + bOff[0] + ks*32);
                ldsm_x4(bm[1][0], bm[1][1], bm[1][2], bm[1][3], wbuf + bOff[1] + ks*32);
                #pragma unroll
                for (int nt = 0; nt < 4; nt++) {
                    uint32_t b0 = bm[nt>>1][(nt&1)*2];
                    uint32_t b1 = bm[nt>>1][(nt&1)*2 + 1];
                    mma_f16(acc[0][nt], a[0], b0, b1);
                    mma_f16(acc[1][nt], a[1], b0, b1);
                }
            }
            __syncthreads();
        }
        // fold this jt: fr += Y[p,j] * subs[p,j]
        #pragma unroll
        for (int mt = 0; mt < 2; mt++) {
            int r0 = (ph*32 + mt*16 + g)*260;
            #pragma unroll
            for (int nt = 0; nt < 4; nt++) {
                int jw = (jt*128 + jq*32 + nt*8) / 2 + t2;
                uint32_t w0 = sS32[r0 + jw];
                uint32_t w8 = sS32[r0 + 8*260 + jw];
                fr[mt][0] += acc[mt][nt][0]*h_lo(w0) + acc[mt][nt][1]*h_hi(w0);
                fr[mt][1] += acc[mt][nt][2]*h_lo(w8) + acc[mt][nt][3]*h_hi(w8);
            }
        }
    }
    __syncthreads();

    #pragma unroll
    for (int mt = 0; mt < 2; mt++)
        #pragma unroll
        for (int h = 0; h < 2; h++) {
            float v = fr[mt][h];
            v += __shfl_down_sync(0xffffffffu, v, 2);
            v += __shfl_down_sync(0xffffffffu, v, 1);
            if (t2 == 0) sRed[(ph*32 + mt*16 + h*8 + g)*4 + jq] = v;
        }
    __syncthreads();
    if (tid < 64)
        kraw[n1*NSEQ + n2base + tid] =
            sRed[tid*4+0] + sRed[tid*4+1] + sRed[tid*4+2] + sRed[tid*4+3];
}

// ---------------- launch 5: kpart[jt][s] partial d^T w d (fp32) ----------------
__global__ void __launch_bounds__(256) k_quad() {
    extern __shared__ float qm[];
    float* sw  = qm;                 // [512 i][36]
    float* sDc = qm + 512*36;        // [64 s][132]
    int jt = blockIdx.x, sg = blockIdx.y;
    int t = threadIdx.x, sl = t >> 2, jl = t & 3;

    for (int f = t; f < 512*8; f += 256) {
        int i = f >> 3, c4 = f & 7;
        float4 v = *(const float4*)(g_w + (size_t)i*LL + jt*32 + c4*4);
        *(float4*)(sw + i*36 + c4*4) = v;
    }
    float y[8];
    #pragma unroll
    for (int k = 0; k < 8; k++) y[k] = 0.f;
    for (int ic = 0; ic < 4; ic++) {
        __syncthreads();
        for (int f = t; f < 64*32; f += 256) {
            int s = f >> 5, c4 = f & 31;
            float4 v = *(const float4*)(&g_d[sg*64 + s][ic*128 + c4*4]);
            *(float4*)(sDc + s*132 + c4*4) = v;
        }
        __syncthreads();
        #pragma unroll 4
        for (int i = 0; i < 128; i++) {
            float dv = sDc[sl*132 + i];
            const float* wr = sw + (ic*128 + i)*36 + jl;
            #pragma unroll
            for (int k = 0; k < 8; k++) y[k] += dv * wr[k*4];
        }
    }
    float pv = 0.f;
    #pragma unroll
    for (int k = 0; k < 8; k++)
        pv += y[k] * g_d[sg*64 + sl][jt*32 + jl + k*4];
    pv += __shfl_down_sync(0xffffffffu, pv, 2);
    pv += __shfl_down_sync(0xffffffffu, pv, 1);
    if (jl == 0) g_kpart[jt*512 + sg*64 + sl] = pv;
}

// ---------------- launch 6: normalize ----------------
__global__ void k_fin(const float* __restrict__ ap, float* __restrict__ out) {
    int n1 = blockIdx.x, n2 = threadIdx.x;
    float s1 = 0.f, s2 = 0.f;
    #pragma unroll
    for (int q = 0; q < 16; q++) {
        s1 += g_kpart[q*512 + n1];
        s2 += g_kpart[q*512 + NSEQ + n2];
    }
    float a0 = ap[0];
    out[n1*NSEQ + n2] = a0*a0 * g_Kraw[n1*NSEQ + n2] * rsqrtf(s1) * rsqrtf(s2);
}

// ---------------- launch ----------------
extern "C" void kernel_launch(void* const* d_in, const int* in_sizes, int n_in,
                              void* d_out, int out_size) {
    const int*   X1 = (const int*)d_in[0];
    const int*   X2 = (const int*)d_in[1];
    const float* W  = (const float*)d_in[2];
    const float* b  = (const float*)d_in[3];
    const float* wp = (const float*)d_in[4];
    const float* a  = (const float*)d_in[5];
    float* out = (float*)d_out;

    float* kraw;  cudaGetSymbolAddress((void**)&kraw, g_Kraw);

    const int SMEM_MMA  = 66560 + 2*18432;              // 103424 B -> 2 blocks/SM
    const int SMEM_QUAD = (512*36 + 64*132) * 4;        // 107520 B
    cudaFuncSetAttribute(k_mma,  cudaFuncAttributeMaxDynamicSharedMemorySize, SMEM_MMA);
    cudaFuncSetAttribute(k_quad, cudaFuncAttributeMaxDynamicSharedMemorySize, SMEM_QUAD);

    k_init<<<1024 + 512, 256>>>(wp, X1, X2);
    k_Eg<<<dim3(84, 2, 4), 256>>>(W, b);
    k_SG<<<2*NSEQ, 256>>>(X1, X2);
    k_mma<<<dim3(4, 256), 256, SMEM_MMA>>>(X1, kraw);
    k_quad<<<dim3(16, 8), 256, SMEM_QUAD>>>();
    k_fin<<<NSEQ, NSEQ>>>(a, out);
}

// round 10
// speedup vs baseline: 3.1536x; 1.0180x over previous
#include <cuda_runtime.h>
#include <cuda_fp16.h>
#include <math.h>
#include <cstdint>

#define NSEQ 256
#define LL   512
#define NAA  21
#define DD   128
#define EDIM (NAA*DD)   // 2688

// ---------------- scratch (static device globals; no allocation) ----------------
__device__ __align__(16) float  g_w[LL*LL];              // fp32 sigmoid'd w (k_quad)
__device__ __align__(16) __half g_wh[LL*LL];             // fp16 w for MMA
__device__ __align__(16) float  g_E4[4][2*NSEQ][EDIM];   // E partials (4 l-quarters)
__device__ __align__(16) __half g_G1h[(size_t)NSEQ*LL*NAA];   // G1[n1][l][c] fp16
__device__ __align__(16) __half g_G2Th[(size_t)LL*NAA*NSEQ];  // G2T[l][c][n2] fp16
__device__ __align__(16) int    g_X1T[LL*NSEQ];
__device__ __align__(16) int    g_X2T[LL*NSEQ];
__device__ __align__(16) float  g_d[2*NSEQ][LL];
__device__ __align__(16) float  g_kpart[16*2*NSEQ];
__device__ __align__(16) float  g_Kraw[NSEQ*NSEQ];

// ---------------- helpers ----------------
__device__ __forceinline__ void mma_f16(float* d, const uint32_t* a, uint32_t b0, uint32_t b1) {
    asm volatile(
        "mma.sync.aligned.m16n8k16.row.col.f32.f16.f16.f32 "
        "{%0,%1,%2,%3}, {%4,%5,%6,%7}, {%8,%9}, {%0,%1,%2,%3};"
        : "+f"(d[0]), "+f"(d[1]), "+f"(d[2]), "+f"(d[3])
        : "r"(a[0]), "r"(a[1]), "r"(a[2]), "r"(a[3]), "r"(b0), "r"(b1));
}
__device__ __forceinline__ void ldsm_x4(uint32_t& r0, uint32_t& r1, uint32_t& r2, uint32_t& r3,
                                        uint32_t addr) {
    asm volatile("ldmatrix.sync.aligned.m8n8.x4.shared.b16 {%0,%1,%2,%3}, [%4];"
                 : "=r"(r0), "=r"(r1), "=r"(r2), "=r"(r3) : "r"(addr));
}
__device__ __forceinline__ uint32_t smem_u32(const void* p) {
    uint32_t a;
    asm("{ .reg .u64 t; cvta.to.shared.u64 t, %1; cvt.u32.u64 %0, t; }" : "=r"(a) : "l"(p));
    return a;
}
__device__ __forceinline__ void cp16(uint32_t dst, const void* src) {
    asm volatile("cp.async.cg.shared.global [%0], [%1], 16;" :: "r"(dst), "l"(src));
}
#define CP_COMMIT() asm volatile("cp.async.commit_group;" ::: "memory")
#define CP_WAIT0()  asm volatile("cp.async.wait_group 0;" ::: "memory")
#define CP_WAIT1()  asm volatile("cp.async.wait_group 1;" ::: "memory")
__device__ __forceinline__ float h_lo(uint32_t w) { return __half2float(__ushort_as_half((unsigned short)(w & 0xffff))); }
__device__ __forceinline__ float h_hi(uint32_t w) { return __half2float(__ushort_as_half((unsigned short)(w >> 16))); }

// ---------------- launch 1: w (fp32 + fp16) + X transposes ----------------
__global__ void k_init(const float* __restrict__ wp,
                       const int* __restrict__ X1, const int* __restrict__ X2) {
    int bid = blockIdx.x;
    if (bid < 1024) {
        int idx = bid*256 + threadIdx.x;
        int i = idx >> 9, j = idx & (LL-1);
        float v = 0.f;
        if (i > j)      v = wp[i*(i-1)/2 + j];
        else if (j > i) v = wp[j*(j-1)/2 + i];
        float s = 1.f / (1.f + expf(-v));
        g_w[idx]  = s;
        g_wh[idx] = __float2half_rn(s);
    } else {
        int q = bid - 1024;
        int n = q & 255, set = q >> 8;
        const int* X = set ? (X2 + n*LL) : (X1 + n*LL);
        int* T = set ? g_X2T : g_X1T;
        for (int l = threadIdx.x; l < LL; l += 256) T[l*NSEQ + n] = X[l];
    }
}

// ---------------- launch 2: E gather-sum partials over 4 l-quarters ----------------
__global__ void __launch_bounds__(256) k_Eg(const float* __restrict__ W, const float* __restrict__ b) {
    int col0 = blockIdx.x * 32;
    int sg   = blockIdx.y;
    int lz   = blockIdx.z;
    const int* XT = sg ? g_X2T : g_X1T;
    __shared__ float sR[168*35];       // 8 l x 21 rows x 32 cols, stride 35 (3*x injective mod 32)
    __shared__ int   sXc[8*256];
    int t = threadIdx.x;
    float acc[32];
    if (lz == 0) {
        #pragma unroll
        for (int c = 0; c < 32; c++) acc[c] = b[col0 + c];
    } else {
        #pragma unroll
        for (int c = 0; c < 32; c++) acc[c] = 0.f;
    }
    int lbase = lz * 128;
    for (int l0 = lbase; l0 < lbase + 128; l0 += 8) {
        __syncthreads();
        for (int f = t; f < 168*32; f += 256) {
            int row = f >> 5, c = f & 31;
            int l = row / 21, r = row - l*21;
            sR[row*35 + c] = W[(size_t)((l0+l)*NAA + r)*EDIM + col0 + c];
        }
        #pragma unroll
        for (int q = 0; q < 8; q++) sXc[q*256 + t] = XT[(l0+q)*NSEQ + t];
        __syncthreads();
        #pragma unroll
        for (int i = 0; i < 8; i++) {
            const float* base = sR + (i*21 + sXc[i*256 + t])*35;
            #pragma unroll
            for (int c = 0; c < 32; c++) acc[c] += base[c];
        }
    }
    float* Er = g_E4[lz][sg*NSEQ + t] + col0;
    #pragma unroll
    for (int c = 0; c < 8; c++)
        ((float4*)Er)[c] = make_float4(acc[4*c], acc[4*c+1], acc[4*c+2], acc[4*c+3]);
}

// ---------------- launch 3: fused S + gather tables (fp16) + diag ----------------
__global__ void __launch_bounds__(256) k_SG(const int* __restrict__ X1, const int* __restrict__ X2) {
    int seq = blockIdx.x;
    __shared__ float sE[EDIM];
    __shared__ float sS[NAA*NAA];
    __shared__ int   sX[LL];
    int tid = threadIdx.x, warp = tid >> 5, lane = tid & 31;
    const int* X = (seq < NSEQ) ? (X1 + seq*LL) : (X2 + (seq-NSEQ)*LL);
    for (int i = tid; i < EDIM/4; i += 256) {
        float4 a = ((const float4*)g_E4[0][seq])[i];
        float4 b = ((const float4*)g_E4[1][seq])[i];
        float4 c = ((const float4*)g_E4[2][seq])[i];
        float4 d = ((const float4*)g_E4[3][seq])[i];
        ((float4*)sE)[i] = make_float4(a.x+b.x+c.x+d.x, a.y+b.y+c.y+d.y,
                                       a.z+b.z+c.z+d.z, a.w+b.w+c.w+d.w);
    }
    for (int i = tid; i < LL; i += 256) sX[i] = X[i];
    __syncthreads();
    for (int e = warp; e < NAA*NAA; e += 8) {
        int a = e / NAA, c = e - a*NAA;
        float4 pa = *(const float4*)(sE + a*DD + lane*4);
        float4 pc = *(const float4*)(sE + c*DD + lane*4);
        float s = pa.x*pc.x + pa.y*pc.y + pa.z*pc.z + pa.w*pc.w;
        #pragma unroll
        for (int o = 16; o; o >>= 1) s += __shfl_xor_sync(0xffffffffu, s, o);
        if (lane == 0) sS[e] = s;
    }
    __syncthreads();
    if (seq < NSEQ) {
        __half* G = g_G1h + (size_t)seq*LL*NAA;
        for (int idx = tid; idx < LL*NAA; idx += 256) {
            int l = idx / NAA, c = idx - l*NAA;
            G[idx] = __float2half_rn(sS[sX[l]*NAA + c]);
        }
    } else {
        int n2 = seq - NSEQ;
        for (int idx = tid; idx < LL*NAA; idx += 256) {
            int l = idx / NAA, c = idx - l*NAA;
            g_G2Th[(size_t)idx*NSEQ + n2] = __float2half_rn(sS[c*NAA + sX[l]]);
        }
    }
    for (int l = tid; l < LL; l += 256)
        g_d[seq][l] = sS[sX[l]*NAA + sX[l]];
}

// ---------------- launch 4: fp16 HMMA GEMM, warp-private w staging, no block barriers ----
// Block = (n1, 64 n2). 8 warps; warp owns 16 j-cols (all jt) and ALL 64 m-rows.
__global__ void __launch_bounds__(256, 2)
k_mma(const int* __restrict__ X1, float* __restrict__ kraw) {
    extern __shared__ char smraw[];
    __half* sS = (__half*)smraw;                 // 64*520*2 = 66560 B
    char* uni = smraw + 66560;                   // warp-private w: 8 warps x 2 bufs x 2304 B
    __half* sG1 = (__half*)uni;                  // phase-1 union (21504 B)
    int*   sX1  = (int*)(uni + 21504);           // 2048 B
    float* sRed = (float*)uni;                   // epilogue union (64*8 f)

    const uint32_t* sS32 = (const uint32_t*)sS;

    int tid  = threadIdx.x;
    int warp = tid >> 5, lane = tid & 31;
    int g = lane >> 2, t2 = lane & 3;
    int n1 = blockIdx.y;
    int n2base = blockIdx.x * 64;

    // ---- phase 1: stage G1[n1] (fp16) + X1 row, build subs^T in fp16 ----
    const uint4* G1p = (const uint4*)(g_G1h + (size_t)n1*LL*NAA);
    for (int f = tid; f < LL*NAA*2/16; f += 256) ((uint4*)sG1)[f] = G1p[f];
    for (int i = tid; i < LL; i += 256) sX1[i] = X1[n1*LL + i];
    __syncthreads();
    {
        int p = tid & 63;
        int n2 = n2base + p;
        for (int l = tid >> 6; l < LL; l += 4) {
            int x2 = g_X2T[l*NSEQ + n2];
            float g1 = __half2float(sG1[l*NAA + x2]);
            float g2 = __half2float(g_G2Th[(size_t)(l*NAA + sX1[l])*NSEQ + n2]);
            sS[p*520 + l] = __float2half_rn(0.5f*(g1 + g2));
        }
    }
    __syncthreads();

    // ---- addressing ----
    uint32_t sSaddr = smem_u32(sS);
    uint32_t wbase  = smem_u32(uni) + (uint32_t)warp*4608;   // 2 bufs x 2304 B
    // A: x4 = m16 x k16 fragment
    int laneRowA = lane & 15;
    int laneKA   = (lane >> 4) * 8;
    uint32_t aAddr[4];
    #pragma unroll
    for (int mt = 0; mt < 4; mt++)
        aAddr[mt] = sSaddr + (uint32_t)(((mt*16 + laneRowA)*520 + laneKA)*2);
    // B: x4 = (n0-7,k0-7),(n0-7,k8-15),(n8-15,k0-7),(n8-15,k8-15); 16 rows, stride 144 B
    int laneRowB = (lane & 7) + (lane >> 4) * 8;
    int laneKB   = ((lane >> 3) & 1) * 8;
    uint32_t bOff = (uint32_t)(laneRowB*144 + laneKB*2);

    // warp's w slice for chunk c (jt = c>>3, kc = c&7): rows jt*128 + warp*16, k = kc*64
    const __half* wsrc = g_wh + (size_t)(warp*16)*LL;

    float fr[4][2];
    #pragma unroll
    for (int mt = 0; mt < 4; mt++) { fr[mt][0] = 0.f; fr[mt][1] = 0.f; }
    float acc[4][2][4];
    #pragma unroll
    for (int mt = 0; mt < 4; mt++)
        #pragma unroll
        for (int nt = 0; nt < 2; nt++)
            #pragma unroll
            for (int c = 0; c < 4; c++) acc[mt][nt][c] = 0.f;

    // prologue: stage chunk 0
    {
        const __half* src0 = wsrc;     // jt=0, kc=0
        #pragma unroll
        for (int q = 0; q < 4; q++) {
            int idx = q*32 + lane;
            int row = idx >> 3, c8 = idx & 7;
            cp16(wbase + (uint32_t)(row*144 + c8*16), src0 + row*LL + c8*8);
        }
        CP_COMMIT();
    }

    for (int c = 0; c < 32; c++) {
        int jt = c >> 3, kc = c & 7;
        if (c < 31) {
            int cn = c + 1;
            int jtn = cn >> 3, kcn = cn & 7;
            const __half* srcn = wsrc + (size_t)(jtn*128)*LL + kcn*64;
            uint32_t dstb = wbase + (uint32_t)((cn & 1) * 2304);
            #pragma unroll
            for (int q = 0; q < 4; q++) {
                int idx = q*32 + lane;
                int row = idx >> 3, c8 = idx & 7;
                cp16(dstb + (uint32_t)(row*144 + c8*16), srcn + row*LL + c8*8);
            }
            CP_COMMIT();
            CP_WAIT1();
        } else {
            CP_WAIT0();
        }
        __syncwarp();
        uint32_t wbuf = wbase + (uint32_t)((c & 1) * 2304);
        #pragma unroll
        for (int ks = 0; ks < 4; ks++) {
            uint32_t kbyteA = (uint32_t)((kc*64 + ks*16)*2);
            uint32_t bm[4];
            ldsm_x4(bm[0], bm[1], bm[2], bm[3], wbuf + bOff + ks*32);
            #pragma unroll
            for (int mt = 0; mt < 4; mt++) {
                uint32_t a[4];
                ldsm_x4(a[0], a[1], a[2], a[3], aAddr[mt] + kbyteA);
                mma_f16(acc[mt][0], a, bm[0], bm[1]);
                mma_f16(acc[mt][1], a, bm[2], bm[3]);
            }
        }
        if (kc == 7) {
            // fold this jt: fr += Y[m,j] * subs[m,j]; then reset acc
            #pragma unroll
            for (int mt = 0; mt < 4; mt++) {
                int r0 = (mt*16 + g)*260;
                #pragma unroll
                for (int nt = 0; nt < 2; nt++) {
                    int jw = (jt*128 + warp*16 + nt*8) / 2 + t2;
                    uint32_t w0 = sS32[r0 + jw];
                    uint32_t w8 = sS32[r0 + 8*260 + jw];
                    fr[mt][0] += acc[mt][nt][0]*h_lo(w0) + acc[mt][nt][1]*h_hi(w0);
                    fr[mt][1] += acc[mt][nt][2]*h_lo(w8) + acc[mt][nt][3]*h_hi(w8);
                    #pragma unroll
                    for (int q = 0; q < 4; q++) acc[mt][nt][q] = 0.f;
                }
            }
        }
    }
    __syncthreads();   // all warps done with uni (w buffers) before sRed reuse

    #pragma unroll
    for (int mt = 0; mt < 4; mt++)
        #pragma unroll
        for (int h = 0; h < 2; h++) {
            float v = fr[mt][h];
            v += __shfl_down_sync(0xffffffffu, v, 2);
            v += __shfl_down_sync(0xffffffffu, v, 1);
            if (t2 == 0) sRed[(mt*16 + h*8 + g)*8 + warp] = v;
        }
    __syncthreads();
    if (tid < 64) {
        float s = 0.f;
        #pragma unroll
        for (int q = 0; q < 8; q++) s += sRed[tid*8 + q];
        kraw[n1*NSEQ + n2base + tid] = s;
    }
}

// ---------------- launch 5: kpart[jt][s] partial d^T w d (fp32) ----------------
__global__ void __launch_bounds__(256) k_quad() {
    extern __shared__ float qm[];
    float* sw  = qm;                 // [512 i][36]
    float* sDc = qm + 512*36;        // [64 s][132]
    int jt = blockIdx.x, sg = blockIdx.y;
    int t = threadIdx.x, sl = t >> 2, jl = t & 3;

    for (int f = t; f < 512*8; f += 256) {
        int i = f >> 3, c4 = f & 7;
        float4 v = *(const float4*)(g_w + (size_t)i*LL + jt*32 + c4*4);
        *(float4*)(sw + i*36 + c4*4) = v;
    }
    float y[8];
    #pragma unroll
    for (int k = 0; k < 8; k++) y[k] = 0.f;
    for (int ic = 0; ic < 4; ic++) {
        __syncthreads();
        for (int f = t; f < 64*32; f += 256) {
            int s = f >> 5, c4 = f & 31;
            float4 v = *(const float4*)(&g_d[sg*64 + s][ic*128 + c4*4]);
            *(float4*)(sDc + s*132 + c4*4) = v;
        }
        __syncthreads();
        #pragma unroll 4
        for (int i = 0; i < 128; i++) {
            float dv = sDc[sl*132 + i];
            const float* wr = sw + (ic*128 + i)*36 + jl;
            #pragma unroll
            for (int k = 0; k < 8; k++) y[k] += dv * wr[k*4];
        }
    }
    float pv = 0.f;
    #pragma unroll
    for (int k = 0; k < 8; k++)
        pv += y[k] * g_d[sg*64 + sl][jt*32 + jl + k*4];
    pv += __shfl_down_sync(0xffffffffu, pv, 2);
    pv += __shfl_down_sync(0xffffffffu, pv, 1);
    if (jl == 0) g_kpart[jt*512 + sg*64 + sl] = pv;
}

// ---------------- launch 6: normalize ----------------
__global__ void k_fin(const float* __restrict__ ap, float* __restrict__ out) {
    int n1 = blockIdx.x, n2 = threadIdx.x;
    float s1 = 0.f, s2 = 0.f;
    #pragma unroll
    for (int q = 0; q < 16; q++) {
        s1 += g_kpart[q*512 + n1];
        s2 += g_kpart[q*512 + NSEQ + n2];
    }
    float a0 = ap[0];
    out[n1*NSEQ + n2] = a0*a0 * g_Kraw[n1*NSEQ + n2] * rsqrtf(s1) * rsqrtf(s2);
}

// ---------------- launch ----------------
extern "C" void kernel_launch(void* const* d_in, const int* in_sizes, int n_in,
                              void* d_out, int out_size) {
    const int*   X1 = (const int*)d_in[0];
    const int*   X2 = (const int*)d_in[1];
    const float* W  = (const float*)d_in[2];
    const float* b  = (const float*)d_in[3];
    const float* wp = (const float*)d_in[4];
    const float* a  = (const float*)d_in[5];
    float* out = (float*)d_out;

    float* kraw;  cudaGetSymbolAddress((void**)&kraw, g_Kraw);

    const int SMEM_MMA  = 66560 + 8*2*2304;             // 103424 B -> 2 blocks/SM
    const int SMEM_QUAD = (512*36 + 64*132) * 4;        // 107520 B
    cudaFuncSetAttribute(k_mma,  cudaFuncAttributeMaxDynamicSharedMemorySize, SMEM_MMA);
    cudaFuncSetAttribute(k_quad, cudaFuncAttributeMaxDynamicSharedMemorySize, SMEM_QUAD);

    k_init<<<1024 + 512, 256>>>(wp, X1, X2);
    k_Eg<<<dim3(84, 2, 4), 256>>>(W, b);
    k_SG<<<2*NSEQ, 256>>>(X1, X2);
    k_mma<<<dim3(4, 256), 256, SMEM_MMA>>>(X1, kraw);
    k_quad<<<dim3(16, 8), 256, SMEM_QUAD>>>();
    k_fin<<<NSEQ, NSEQ>>>(a, out);
}